// round 1
// baseline (speedup 1.0000x reference)
#include <cuda_runtime.h>
#include <math.h>

// Problem constants
constexpr int kTOK = 8192;        // B*S tokens
constexpr int kD   = 1024;
constexpr int kF   = 4096;
constexpr int kE   = 8;
constexpr int kASSIGN = kTOK * 2; // top-2 assignments

// ---------------- scratch (device globals; no allocation allowed) ----------
__device__ int   g_topk_e[kASSIGN];
__device__ float g_topk_w[kASSIGN];
__device__ int   g_counts[kE];
__device__ int   g_offsets[kE + 1];
__device__ int   g_cursors[kE];
__device__ int   g_tok[kASSIGN];
__device__ float g_wt[kASSIGN];
__device__ float g_h[(size_t)kASSIGN * kF];   // 268 MB intermediate activations

// ---------------- init: zero counters ----------------
__global__ void init_kernel() {
    int i = threadIdx.x;
    if (i < kE) { g_counts[i] = 0; g_cursors[i] = 0; }
}

// ---------------- gating: 1 warp per token ----------------
__global__ void gate_kernel(const float* __restrict__ x,
                            const float* __restrict__ Wg,
                            const float* __restrict__ bg) {
    int w    = (blockIdx.x * blockDim.x + threadIdx.x) >> 5;
    int lane = threadIdx.x & 31;
    if (w >= kTOK) return;
    const float* xr = x + (size_t)w * kD;
    float acc[kE];
#pragma unroll
    for (int e = 0; e < kE; e++) acc[e] = 0.f;
    for (int d = lane * 4; d < kD; d += 128) {
        float4 xv = *(const float4*)(xr + d);
#pragma unroll
        for (int e = 0; e < kE; e++) {
            float4 wv = *(const float4*)(Wg + e * kD + d);
            acc[e] += xv.x * wv.x + xv.y * wv.y + xv.z * wv.z + xv.w * wv.w;
        }
    }
#pragma unroll
    for (int e = 0; e < kE; e++)
#pragma unroll
        for (int o = 16; o; o >>= 1) acc[e] += __shfl_xor_sync(0xffffffffu, acc[e], o);
    if (lane == 0) {
        float l[kE];
#pragma unroll
        for (int e = 0; e < kE; e++) l[e] = acc[e] + bg[e];
        int i1 = 0;
#pragma unroll
        for (int e = 1; e < kE; e++) if (l[e] > l[i1]) i1 = e;
        int i2 = (i1 == 0) ? 1 : 0;
#pragma unroll
        for (int e = 0; e < kE; e++) if (e != i1 && l[e] > l[i2]) i2 = e;
        // renormalized top-2 softmax weights
        float w1 = 1.f / (1.f + expf(l[i2] - l[i1]));
        float w2 = 1.f - w1;
        g_topk_e[2 * w]     = i1;
        g_topk_e[2 * w + 1] = i2;
        g_topk_w[2 * w]     = w1;
        g_topk_w[2 * w + 1] = w2;
        atomicAdd(&g_counts[i1], 1);
        atomicAdd(&g_counts[i2], 1);
    }
}

// ---------------- tiny exclusive scan ----------------
__global__ void scan_kernel() {
    int s = 0;
#pragma unroll
    for (int e = 0; e < kE; e++) { g_offsets[e] = s; s += g_counts[e]; }
    g_offsets[kE] = s;
}

// ---------------- scatter token ids into per-expert lists ----------------
__global__ void scatter_kernel() {
    int i = blockIdx.x * blockDim.x + threadIdx.x;
    if (i >= kASSIGN) return;
    int e   = g_topk_e[i];
    int pos = g_offsets[e] + atomicAdd(&g_cursors[e], 1);
    g_tok[pos] = i >> 1;
    g_wt[pos]  = g_topk_w[i];
}

// ---------------- shared 8x8-microtile fp32 compute core -------------------
__device__ __forceinline__ void mm_compute(float (*As)[132], float (*Bs)[132],
                                           float acc[8][8], int tx, int ty) {
#pragma unroll
    for (int kk = 0; kk < 8; kk++) {
        float a[8], b[8];
        *(float4*)&a[0] = *(const float4*)&As[kk][ty * 4];
        *(float4*)&a[4] = *(const float4*)&As[kk][64 + ty * 4];
        *(float4*)&b[0] = *(const float4*)&Bs[kk][tx * 4];
        *(float4*)&b[4] = *(const float4*)&Bs[kk][64 + tx * 4];
#pragma unroll
        for (int i = 0; i < 8; i++)
#pragma unroll
            for (int j = 0; j < 8; j++) acc[i][j] += a[i] * b[j];
    }
}

// ---------------- GEMM1: h = gelu(gather(x) @ W1[e] + b1[e]) ---------------
__global__ __launch_bounds__(256) void gemm1_kernel(const float* __restrict__ x,
                                                    const float* __restrict__ W1,
                                                    const float* __restrict__ b1) {
    int e   = blockIdx.z;
    int off = g_offsets[e];
    int cnt = g_offsets[e + 1] - off;
    int m0  = blockIdx.y * 128;
    if (m0 >= cnt) return;
    int n0  = blockIdx.x * 128;

    __shared__ float As[8][132], Bs[8][132];
    __shared__ int   stok[128];
    int tid = threadIdx.x;
    if (tid < 128) {
        int m = m0 + tid;
        stok[tid] = (m < cnt) ? g_tok[off + m] : -1;
    }
    __syncthreads();

    const float* Wb = W1 + (size_t)e * kD * kF;
    float acc[8][8];
#pragma unroll
    for (int i = 0; i < 8; i++)
#pragma unroll
        for (int j = 0; j < 8; j++) acc[i][j] = 0.f;

    int am = tid >> 1, ak = (tid & 1) * 4;
    int bk = tid >> 5, bn = (tid & 31) * 4;
    int tx = tid & 15, ty = tid >> 4;
    int atok = stok[am];
    const float* aptr = (atok >= 0) ? (x + (size_t)atok * kD + ak) : nullptr;

    for (int k0 = 0; k0 < kD; k0 += 8) {
        float4 av = make_float4(0.f, 0.f, 0.f, 0.f);
        if (aptr) av = *(const float4*)(aptr + k0);
        float4 bv = *(const float4*)(Wb + (size_t)(k0 + bk) * kF + n0 + bn);
        __syncthreads();
        As[ak + 0][am] = av.x; As[ak + 1][am] = av.y;
        As[ak + 2][am] = av.z; As[ak + 3][am] = av.w;
        *(float4*)&Bs[bk][bn] = bv;
        __syncthreads();
        mm_compute(As, Bs, acc, tx, ty);
    }

    const float* b1e = b1 + (size_t)e * kF + n0;
#pragma unroll
    for (int i = 0; i < 8; i++) {
        int ml = (i < 4) ? ty * 4 + i : 64 + ty * 4 + (i - 4);
        int mg = m0 + ml;
        if (mg < cnt) {
            float* hr = g_h + (size_t)(off + mg) * kF + n0;
#pragma unroll
            for (int j = 0; j < 8; j++) {
                int nl = (j < 4) ? tx * 4 + j : 64 + tx * 4 + (j - 4);
                float v = acc[i][j] + b1e[nl];
                v = 0.5f * v * (1.0f + erff(v * 0.70710678118654752f));
                hr[nl] = v;
            }
        }
    }
}

// ---------------- GEMM2: out += w * (h @ W2[e] + b2[e]) --------------------
__global__ __launch_bounds__(256) void gemm2_kernel(const float* __restrict__ W2,
                                                    const float* __restrict__ b2,
                                                    float* __restrict__ out) {
    int e   = blockIdx.z;
    int off = g_offsets[e];
    int cnt = g_offsets[e + 1] - off;
    int m0  = blockIdx.y * 128;
    if (m0 >= cnt) return;
    int n0  = blockIdx.x * 128;

    __shared__ float As[8][132], Bs[8][132];
    __shared__ int   stok[128];
    __shared__ float swt[128];
    int tid = threadIdx.x;
    if (tid < 128) {
        int m = m0 + tid;
        stok[tid] = (m < cnt) ? g_tok[off + m] : -1;
        swt[tid]  = (m < cnt) ? g_wt[off + m] : 0.f;
    }
    __syncthreads();

    const float* Wb = W2 + (size_t)e * kF * kD;
    float acc[8][8];
#pragma unroll
    for (int i = 0; i < 8; i++)
#pragma unroll
        for (int j = 0; j < 8; j++) acc[i][j] = 0.f;

    int am = tid >> 1, ak = (tid & 1) * 4;
    int bk = tid >> 5, bn = (tid & 31) * 4;
    int tx = tid & 15, ty = tid >> 4;
    bool avalid = (m0 + am) < cnt;
    const float* aptr = g_h + (size_t)(off + m0 + am) * kF + ak;

    for (int k0 = 0; k0 < kF; k0 += 8) {
        float4 av = make_float4(0.f, 0.f, 0.f, 0.f);
        if (avalid) av = *(const float4*)(aptr + k0);
        float4 bv = *(const float4*)(Wb + (size_t)(k0 + bk) * kD + n0 + bn);
        __syncthreads();
        As[ak + 0][am] = av.x; As[ak + 1][am] = av.y;
        As[ak + 2][am] = av.z; As[ak + 3][am] = av.w;
        *(float4*)&Bs[bk][bn] = bv;
        __syncthreads();
        mm_compute(As, Bs, acc, tx, ty);
    }

    const float* b2e = b2 + (size_t)e * kD + n0;
#pragma unroll
    for (int i = 0; i < 8; i++) {
        int ml = (i < 4) ? ty * 4 + i : 64 + ty * 4 + (i - 4);
        int mg = m0 + ml;
        if (mg < cnt) {
            int   tk = stok[ml];
            float w  = swt[ml];
            float* orow = out + (size_t)tk * kD + n0;
#pragma unroll
            for (int j = 0; j < 8; j++) {
                int nl = (j < 4) ? tx * 4 + j : 64 + tx * 4 + (j - 4);
                atomicAdd(&orow[nl], w * (acc[i][j] + b2e[nl]));
            }
        }
    }
}

// ---------------- launch ----------------
extern "C" void kernel_launch(void* const* d_in, const int* in_sizes, int n_in,
                              void* d_out, int out_size) {
    const float* x  = (const float*)d_in[0];
    const float* Wg = (const float*)d_in[1];
    const float* bg = (const float*)d_in[2];
    const float* W1 = (const float*)d_in[3];
    const float* b1 = (const float*)d_in[4];
    const float* W2 = (const float*)d_in[5];
    const float* b2 = (const float*)d_in[6];
    float* out = (float*)d_out;

    cudaMemsetAsync(out, 0, (size_t)out_size * sizeof(float));
    init_kernel<<<1, 32>>>();
    gate_kernel<<<kTOK / 8, 256>>>(x, Wg, bg);
    scan_kernel<<<1, 1>>>();
    scatter_kernel<<<kASSIGN / 256, 256>>>();
    gemm1_kernel<<<dim3(kF / 128, kTOK / 128, kE), 256>>>(x, W1, b1);
    gemm2_kernel<<<dim3(kD / 128, kTOK / 128, kE), 256>>>(W2, b2, out);
}

// round 3
// speedup vs baseline: 1.9543x; 1.9543x over previous
#include <cuda_runtime.h>
#include <cstdint>
#include <math.h>

// ---------------- problem constants ----------------
constexpr int kTOK = 8192;
constexpr int kD   = 1024;
constexpr int kF   = 4096;
constexpr int kE   = 8;
constexpr int kASSIGN = kTOK * 2;

constexpr int BM = 128, BN = 128, BK = 16;

// ---------------- device scratch ----------------
__device__ int   g_topk_e[kASSIGN];
__device__ float g_topk_w[kASSIGN];
__device__ int   g_counts[kE];
__device__ int   g_offsets[kE + 1];
__device__ int   g_cursors[kE];
__device__ int   g_tok[kASSIGN];
__device__ float g_wt[kASSIGN];
__device__ float g_h[(size_t)kASSIGN * kF];   // 268 MB activations

// ---------------- helpers ----------------
__device__ __forceinline__ uint32_t f2tf32(float x) {
    uint32_t r;
    asm("cvt.rna.tf32.f32 %0, %1;" : "=r"(r) : "f"(x));
    return r;
}
__device__ __forceinline__ float f2tf32f(float x) {
    return __uint_as_float(f2tf32(x));
}
__device__ __forceinline__ void mma_tf32(float* c,
                                         uint32_t a0, uint32_t a1, uint32_t a2, uint32_t a3,
                                         uint32_t b0, uint32_t b1) {
    asm volatile("mma.sync.aligned.m16n8k8.row.col.f32.tf32.tf32.f32 "
                 "{%0,%1,%2,%3}, {%4,%5,%6,%7}, {%8,%9}, {%0,%1,%2,%3};"
                 : "+f"(c[0]), "+f"(c[1]), "+f"(c[2]), "+f"(c[3])
                 : "r"(a0), "r"(a1), "r"(a2), "r"(a3), "r"(b0), "r"(b1));
}
__device__ __forceinline__ float gelu_f(float v) {
    return 0.5f * v * (1.0f + erff(v * 0.70710678118654752f));
}

// ---------------- routing kernels ----------------
__global__ void init_kernel() {
    int i = threadIdx.x;
    if (i < kE) { g_counts[i] = 0; g_cursors[i] = 0; }
}

__global__ void gate_kernel(const float* __restrict__ x, const float* __restrict__ Wg,
                            const float* __restrict__ bg) {
    int w = (blockIdx.x * blockDim.x + threadIdx.x) >> 5;
    int lane = threadIdx.x & 31;
    if (w >= kTOK) return;
    const float* xr = x + (size_t)w * kD;
    float acc[kE];
#pragma unroll
    for (int e = 0; e < kE; e++) acc[e] = 0.f;
    for (int d = lane * 4; d < kD; d += 128) {
        float4 xv = *(const float4*)(xr + d);
#pragma unroll
        for (int e = 0; e < kE; e++) {
            float4 wv = *(const float4*)(Wg + e * kD + d);
            acc[e] += xv.x * wv.x + xv.y * wv.y + xv.z * wv.z + xv.w * wv.w;
        }
    }
#pragma unroll
    for (int e = 0; e < kE; e++)
#pragma unroll
        for (int o = 16; o; o >>= 1) acc[e] += __shfl_xor_sync(0xffffffffu, acc[e], o);
    if (lane == 0) {
        float l[kE];
#pragma unroll
        for (int e = 0; e < kE; e++) l[e] = acc[e] + bg[e];
        int i1 = 0;
#pragma unroll
        for (int e = 1; e < kE; e++) if (l[e] > l[i1]) i1 = e;
        int i2 = (i1 == 0) ? 1 : 0;
#pragma unroll
        for (int e = 0; e < kE; e++) if (e != i1 && l[e] > l[i2]) i2 = e;
        float w1 = 1.f / (1.f + expf(l[i2] - l[i1]));
        g_topk_e[2 * w] = i1; g_topk_e[2 * w + 1] = i2;
        g_topk_w[2 * w] = w1; g_topk_w[2 * w + 1] = 1.f - w1;
        atomicAdd(&g_counts[i1], 1);
        atomicAdd(&g_counts[i2], 1);
    }
}

__global__ void scan_kernel() {
    int s = 0;
#pragma unroll
    for (int e = 0; e < kE; e++) { g_offsets[e] = s; s += g_counts[e]; }
    g_offsets[kE] = s;
}

__global__ void scatter_kernel() {
    int i = blockIdx.x * blockDim.x + threadIdx.x;
    if (i >= kASSIGN) return;
    int e = g_topk_e[i];
    int pos = g_offsets[e] + atomicAdd(&g_cursors[e], 1);
    g_tok[pos] = i >> 1;
    g_wt[pos] = g_topk_w[i];
}

// ======================= tf32 mma.sync GEMM kernels ========================
// Tile 128x128x16, 256 threads = 8 warps (2 M x 4 N), warp tile 64x32.
// As stored K-major transposed [k][m] with 136-float row pad (conflict-free
// fragment loads: bank = 8*tig + grp, all distinct). Bs stored [k][n], same pad.

// ---------------- GEMM1: h = gelu(gather(x) @ W1[e] + b1) ------------------
__global__ __launch_bounds__(256) void gemm1_tc(const float* __restrict__ x,
                                                const float* __restrict__ W1,
                                                const float* __restrict__ b1) {
    int e = blockIdx.z;
    int off = g_offsets[e];
    int cnt = g_offsets[e + 1] - off;
    int m0 = blockIdx.y * BM;
    if (m0 >= cnt) return;
    int n0 = blockIdx.x * BN;

    __shared__ float As[2][BK][136];
    __shared__ float Bs[2][BK][136];
    __shared__ int   stok[BM];

    int tid = threadIdx.x, wid = tid >> 5, lane = tid & 31;
    int tig = lane & 3, grp = lane >> 2;
    int mbase = (wid & 1) * 64;
    int nbase = (wid >> 1) * 32;

    if (tid < BM) {
        int m = m0 + tid;
        stok[tid] = (m < cnt) ? g_tok[off + m] : -1;
    }
    __syncthreads();

    const float* Wb = W1 + (size_t)e * kD * kF;

    // A staging: thread owns row am, k4 in {ak0, ak0+2} (float4 units)
    int am  = tid & 127;
    int ak0 = tid >> 7;
    int atok = stok[am];
    const float* arow = (atok >= 0) ? x + (size_t)atok * kD : nullptr;
    // B staging: thread owns rows bk, bk+8 at col bn4*4
    int bk  = tid >> 5;
    int bn4 = tid & 31;

    float4 ra[2], rb[2];
    auto loadA = [&](int k0) {
#pragma unroll
        for (int j = 0; j < 2; j++) {
            int k4 = ak0 + j * 2;
            ra[j] = arow ? *(const float4*)(arow + k0 + k4 * 4)
                         : make_float4(0.f, 0.f, 0.f, 0.f);
        }
    };
    auto loadB = [&](int k0) {
        rb[0] = *(const float4*)(Wb + (size_t)(k0 + bk) * kF + n0 + bn4 * 4);
        rb[1] = *(const float4*)(Wb + (size_t)(k0 + bk + 8) * kF + n0 + bn4 * 4);
    };
    auto stsAB = [&](int buf) {
#pragma unroll
        for (int j = 0; j < 2; j++) {
            int k4 = ak0 + j * 2;
            As[buf][k4 * 4 + 0][am] = f2tf32f(ra[j].x);
            As[buf][k4 * 4 + 1][am] = f2tf32f(ra[j].y);
            As[buf][k4 * 4 + 2][am] = f2tf32f(ra[j].z);
            As[buf][k4 * 4 + 3][am] = f2tf32f(ra[j].w);
        }
#pragma unroll
        for (int j = 0; j < 2; j++) {
            float4 v = rb[j];
            float4 t = make_float4(f2tf32f(v.x), f2tf32f(v.y), f2tf32f(v.z), f2tf32f(v.w));
            *(float4*)&Bs[buf][bk + j * 8][bn4 * 4] = t;
        }
    };

    float acc[4][4][4];
#pragma unroll
    for (int i = 0; i < 4; i++)
#pragma unroll
        for (int j = 0; j < 4; j++)
#pragma unroll
            for (int q = 0; q < 4; q++) acc[i][j][q] = 0.f;

    constexpr int C = kD / BK;   // 64
    loadA(0); loadB(0);
    stsAB(0);
    __syncthreads();

    for (int c = 0; c < C; c++) {
        int cur = c & 1;
        bool more = (c + 1 < C);
        if (more) { loadA((c + 1) * BK); loadB((c + 1) * BK); }
#pragma unroll
        for (int ks = 0; ks < 2; ks++) {
            int kr = ks * 8 + tig;
            uint32_t af[4][4], bf[4][2];
#pragma unroll
            for (int mt = 0; mt < 4; mt++) {
                int mc = mbase + mt * 16 + grp;
                af[mt][0] = __float_as_uint(As[cur][kr][mc]);
                af[mt][1] = __float_as_uint(As[cur][kr][mc + 8]);
                af[mt][2] = __float_as_uint(As[cur][kr + 4][mc]);
                af[mt][3] = __float_as_uint(As[cur][kr + 4][mc + 8]);
            }
#pragma unroll
            for (int nt = 0; nt < 4; nt++) {
                int nc = nbase + nt * 8 + grp;
                bf[nt][0] = __float_as_uint(Bs[cur][kr][nc]);
                bf[nt][1] = __float_as_uint(Bs[cur][kr + 4][nc]);
            }
#pragma unroll
            for (int mt = 0; mt < 4; mt++)
#pragma unroll
                for (int nt = 0; nt < 4; nt++)
                    mma_tf32(acc[mt][nt], af[mt][0], af[mt][1], af[mt][2], af[mt][3],
                             bf[nt][0], bf[nt][1]);
        }
        if (more) {
            stsAB(cur ^ 1);
            __syncthreads();
        }
    }

    // epilogue
    const float* bb = b1 + (size_t)e * kF + n0;
#pragma unroll
    for (int mt = 0; mt < 4; mt++) {
        int rbase = mbase + mt * 16 + grp;
#pragma unroll
        for (int h = 0; h < 2; h++) {
            int r = rbase + h * 8;
            int m = m0 + r;
            if (m < cnt) {
                float* hrow = g_h + (size_t)(off + m) * kF + n0;
#pragma unroll
                for (int nt = 0; nt < 4; nt++) {
                    int cc = nbase + nt * 8 + tig * 2;
                    float2 v;
                    v.x = gelu_f(acc[mt][nt][h * 2 + 0] + bb[cc]);
                    v.y = gelu_f(acc[mt][nt][h * 2 + 1] + bb[cc + 1]);
                    *(float2*)(hrow + cc) = v;
                }
            }
        }
    }
}

// ---------------- GEMM2: out += w * (h @ W2[e] + b2) -----------------------
__global__ __launch_bounds__(256) void gemm2_tc(const float* __restrict__ W2,
                                                const float* __restrict__ b2,
                                                float* __restrict__ out) {
    int e = blockIdx.z;
    int off = g_offsets[e];
    int cnt = g_offsets[e + 1] - off;
    int m0 = blockIdx.y * BM;
    if (m0 >= cnt) return;
    int n0 = blockIdx.x * BN;

    __shared__ float As[2][BK][136];
    __shared__ float Bs[2][BK][136];
    __shared__ int   stok[BM];
    __shared__ float swt[BM];

    int tid = threadIdx.x, wid = tid >> 5, lane = tid & 31;
    int tig = lane & 3, grp = lane >> 2;
    int mbase = (wid & 1) * 64;
    int nbase = (wid >> 1) * 32;

    if (tid < BM) {
        int m = m0 + tid;
        stok[tid] = (m < cnt) ? g_tok[off + m] : -1;
        swt[tid]  = (m < cnt) ? g_wt[off + m] : 0.f;
    }
    __syncthreads();

    const float* Wb = W2 + (size_t)e * kF * kD;

    int am  = tid & 127;
    int ak0 = tid >> 7;
    bool avalid = (m0 + am) < cnt;
    const float* arow = g_h + (size_t)(off + m0 + am) * kF;
    int bk  = tid >> 5;
    int bn4 = tid & 31;

    float4 ra[2], rb[2];
    auto loadA = [&](int k0) {
#pragma unroll
        for (int j = 0; j < 2; j++) {
            int k4 = ak0 + j * 2;
            ra[j] = avalid ? *(const float4*)(arow + k0 + k4 * 4)
                           : make_float4(0.f, 0.f, 0.f, 0.f);
        }
    };
    auto loadB = [&](int k0) {
        rb[0] = *(const float4*)(Wb + (size_t)(k0 + bk) * kD + n0 + bn4 * 4);
        rb[1] = *(const float4*)(Wb + (size_t)(k0 + bk + 8) * kD + n0 + bn4 * 4);
    };
    auto stsAB = [&](int buf) {
#pragma unroll
        for (int j = 0; j < 2; j++) {
            int k4 = ak0 + j * 2;
            As[buf][k4 * 4 + 0][am] = f2tf32f(ra[j].x);
            As[buf][k4 * 4 + 1][am] = f2tf32f(ra[j].y);
            As[buf][k4 * 4 + 2][am] = f2tf32f(ra[j].z);
            As[buf][k4 * 4 + 3][am] = f2tf32f(ra[j].w);
        }
#pragma unroll
        for (int j = 0; j < 2; j++) {
            float4 v = rb[j];
            float4 t = make_float4(f2tf32f(v.x), f2tf32f(v.y), f2tf32f(v.z), f2tf32f(v.w));
            *(float4*)&Bs[buf][bk + j * 8][bn4 * 4] = t;
        }
    };

    float acc[4][4][4];
#pragma unroll
    for (int i = 0; i < 4; i++)
#pragma unroll
        for (int j = 0; j < 4; j++)
#pragma unroll
            for (int q = 0; q < 4; q++) acc[i][j][q] = 0.f;

    constexpr int C = kF / BK;   // 256
    loadA(0); loadB(0);
    stsAB(0);
    __syncthreads();

    for (int c = 0; c < C; c++) {
        int cur = c & 1;
        bool more = (c + 1 < C);
        if (more) { loadA((c + 1) * BK); loadB((c + 1) * BK); }
#pragma unroll
        for (int ks = 0; ks < 2; ks++) {
            int kr = ks * 8 + tig;
            uint32_t af[4][4], bf[4][2];
#pragma unroll
            for (int mt = 0; mt < 4; mt++) {
                int mc = mbase + mt * 16 + grp;
                af[mt][0] = __float_as_uint(As[cur][kr][mc]);
                af[mt][1] = __float_as_uint(As[cur][kr][mc + 8]);
                af[mt][2] = __float_as_uint(As[cur][kr + 4][mc]);
                af[mt][3] = __float_as_uint(As[cur][kr + 4][mc + 8]);
            }
#pragma unroll
            for (int nt = 0; nt < 4; nt++) {
                int nc = nbase + nt * 8 + grp;
                bf[nt][0] = __float_as_uint(Bs[cur][kr][nc]);
                bf[nt][1] = __float_as_uint(Bs[cur][kr + 4][nc]);
            }
#pragma unroll
            for (int mt = 0; mt < 4; mt++)
#pragma unroll
                for (int nt = 0; nt < 4; nt++)
                    mma_tf32(acc[mt][nt], af[mt][0], af[mt][1], af[mt][2], af[mt][3],
                             bf[nt][0], bf[nt][1]);
        }
        if (more) {
            stsAB(cur ^ 1);
            __syncthreads();
        }
    }

    // epilogue: weighted atomic scatter
    const float* bbv = b2 + (size_t)e * kD + n0;
#pragma unroll
    for (int mt = 0; mt < 4; mt++) {
        int rbase = mbase + mt * 16 + grp;
#pragma unroll
        for (int h = 0; h < 2; h++) {
            int r = rbase + h * 8;
            int m = m0 + r;
            if (m < cnt) {
                int   tok = stok[r];
                float w   = swt[r];
                float* orow = out + (size_t)tok * kD + n0;
#pragma unroll
                for (int nt = 0; nt < 4; nt++) {
                    int cc = nbase + nt * 8 + tig * 2;
                    atomicAdd(&orow[cc],     w * (acc[mt][nt][h * 2 + 0] + bbv[cc]));
                    atomicAdd(&orow[cc + 1], w * (acc[mt][nt][h * 2 + 1] + bbv[cc + 1]));
                }
            }
        }
    }
}

// ---------------- launch ----------------
extern "C" void kernel_launch(void* const* d_in, const int* in_sizes, int n_in,
                              void* d_out, int out_size) {
    const float* x  = (const float*)d_in[0];
    const float* Wg = (const float*)d_in[1];
    const float* bg = (const float*)d_in[2];
    const float* W1 = (const float*)d_in[3];
    const float* b1 = (const float*)d_in[4];
    const float* W2 = (const float*)d_in[5];
    const float* b2 = (const float*)d_in[6];
    float* out = (float*)d_out;

    cudaMemsetAsync(out, 0, (size_t)out_size * sizeof(float));
    init_kernel<<<1, 32>>>();
    gate_kernel<<<kTOK / 8, 256>>>(x, Wg, bg);
    scan_kernel<<<1, 1>>>();
    scatter_kernel<<<kASSIGN / 256, 256>>>();
    gemm1_tc<<<dim3(kF / BN, kTOK / BM, kE), 256>>>(x, W1, b1);
    gemm2_tc<<<dim3(kD / BN, kTOK / BM, kE), 256>>>(W2, b2, out);
}

// round 4
// speedup vs baseline: 3.1228x; 1.5979x over previous
#include <cuda_runtime.h>
#include <cuda_fp16.h>
#include <cstdint>
#include <math.h>

// ---------------- problem constants ----------------
constexpr int kTOK = 8192;
constexpr int kD   = 1024;
constexpr int kF   = 4096;
constexpr int kE   = 8;
constexpr int kASSIGN = kTOK * 2;

constexpr int BM = 128, BN = 128, BK = 16;

// ---------------- device scratch ----------------
__device__ int   g_topk_e[kASSIGN];
__device__ float g_topk_w[kASSIGN];
__device__ int   g_counts[kE];
__device__ int   g_offsets[kE + 1];
__device__ int   g_cursors[kE];
__device__ int   g_tok[kASSIGN];
__device__ float g_wt[kASSIGN];
__device__ __half g_h[(size_t)kASSIGN * kF];   // 134 MB fp16 activations

// ---------------- helpers ----------------
__device__ __forceinline__ void mma_f16(float* c, uint32_t a0, uint32_t a1,
                                        uint32_t a2, uint32_t a3,
                                        uint32_t b0, uint32_t b1) {
    asm volatile("mma.sync.aligned.m16n8k16.row.col.f32.f16.f16.f32 "
                 "{%0,%1,%2,%3}, {%4,%5,%6,%7}, {%8,%9}, {%0,%1,%2,%3};"
                 : "+f"(c[0]), "+f"(c[1]), "+f"(c[2]), "+f"(c[3])
                 : "r"(a0), "r"(a1), "r"(a2), "r"(a3), "r"(b0), "r"(b1));
}
__device__ __forceinline__ uint32_t h2(float a, float b) {
    __half2 h = __floats2half2_rn(a, b);
    return *(uint32_t*)&h;
}
__device__ __forceinline__ float gelu_f(float v) {
    return 0.5f * v * (1.0f + erff(v * 0.70710678118654752f));
}

// ---------------- routing kernels ----------------
__global__ void init_kernel() {
    int i = threadIdx.x;
    if (i < kE) { g_counts[i] = 0; g_cursors[i] = 0; }
}

__global__ void gate_kernel(const float* __restrict__ x, const float* __restrict__ Wg,
                            const float* __restrict__ bg) {
    int w = (blockIdx.x * blockDim.x + threadIdx.x) >> 5;
    int lane = threadIdx.x & 31;
    if (w >= kTOK) return;
    const float* xr = x + (size_t)w * kD;
    float acc[kE];
#pragma unroll
    for (int e = 0; e < kE; e++) acc[e] = 0.f;
    for (int d = lane * 4; d < kD; d += 128) {
        float4 xv = *(const float4*)(xr + d);
#pragma unroll
        for (int e = 0; e < kE; e++) {
            float4 wv = *(const float4*)(Wg + e * kD + d);
            acc[e] += xv.x * wv.x + xv.y * wv.y + xv.z * wv.z + xv.w * wv.w;
        }
    }
#pragma unroll
    for (int e = 0; e < kE; e++)
#pragma unroll
        for (int o = 16; o; o >>= 1) acc[e] += __shfl_xor_sync(0xffffffffu, acc[e], o);
    if (lane == 0) {
        float l[kE];
#pragma unroll
        for (int e = 0; e < kE; e++) l[e] = acc[e] + bg[e];
        int i1 = 0;
#pragma unroll
        for (int e = 1; e < kE; e++) if (l[e] > l[i1]) i1 = e;
        int i2 = (i1 == 0) ? 1 : 0;
#pragma unroll
        for (int e = 0; e < kE; e++) if (e != i1 && l[e] > l[i2]) i2 = e;
        float w1 = 1.f / (1.f + expf(l[i2] - l[i1]));
        g_topk_e[2 * w] = i1; g_topk_e[2 * w + 1] = i2;
        g_topk_w[2 * w] = w1; g_topk_w[2 * w + 1] = 1.f - w1;
        atomicAdd(&g_counts[i1], 1);
        atomicAdd(&g_counts[i2], 1);
    }
}

__global__ void scan_kernel() {
    int s = 0;
#pragma unroll
    for (int e = 0; e < kE; e++) { g_offsets[e] = s; s += g_counts[e]; }
    g_offsets[kE] = s;
}

__global__ void scatter_kernel() {
    int i = blockIdx.x * blockDim.x + threadIdx.x;
    if (i >= kASSIGN) return;
    int e = g_topk_e[i];
    int pos = g_offsets[e] + atomicAdd(&g_cursors[e], 1);
    g_tok[pos] = i >> 1;
    g_wt[pos] = g_topk_w[i];
}

// ======================= fp16 mma.sync GEMM kernels ========================
// Tile 128x128x16, 256 threads = 8 warps (2 M x 4 N), warp tile 64x32.
// Smem: half2-packed along K.  As2[k2][m] (k2=0..7, pad 136), Bs2[k2][n].
// Fragment banks: k2*136 + idx -> bank 8*k2lo + idx%? -> conflict-free by
// construction (8*tig + grp distinct over warp).

// ---------------- GEMM1: h = gelu(gather(x) @ W1[e] + b1) ------------------
__global__ __launch_bounds__(256) void gemm1_tc(const float* __restrict__ x,
                                                const float* __restrict__ W1,
                                                const float* __restrict__ b1) {
    int e = blockIdx.z;
    int off = g_offsets[e];
    int cnt = g_offsets[e + 1] - off;
    int m0 = blockIdx.y * BM;
    if (m0 >= cnt) return;
    int n0 = blockIdx.x * BN;

    __shared__ uint32_t As2[2][8][136];
    __shared__ uint32_t Bs2[2][8][136];
    __shared__ int stok[BM];

    int tid = threadIdx.x, wid = tid >> 5, lane = tid & 31;
    int tig = lane & 3, grp = lane >> 2;
    int mbase = (wid & 1) * 64;
    int nbase = (wid >> 1) * 32;

    if (tid < BM) {
        int m = m0 + tid;
        stok[tid] = (m < cnt) ? g_tok[off + m] : -1;
    }
    __syncthreads();

    const float* Wb = W1 + (size_t)e * kD * kF;

    // A staging: thread owns row am, float4s at k4 = ak0, ak0+2
    int am  = tid & 127;
    int ak0 = tid >> 7;
    int atok = stok[am];
    const float* arow = (atok >= 0) ? x + (size_t)atok * kD : nullptr;
    // B staging: thread owns k-pair (2bq, 2bq+1), n cols bn4*4..+3
    int bq  = tid >> 5;
    int bn4 = tid & 31;

    float4 ra[2], rb0, rb1;
    auto loadA = [&](int k0) {
#pragma unroll
        for (int j = 0; j < 2; j++) {
            int k4 = ak0 + j * 2;
            ra[j] = arow ? *(const float4*)(arow + k0 + k4 * 4)
                         : make_float4(0.f, 0.f, 0.f, 0.f);
        }
    };
    auto loadB = [&](int k0) {
        rb0 = *(const float4*)(Wb + (size_t)(k0 + 2 * bq) * kF + n0 + bn4 * 4);
        rb1 = *(const float4*)(Wb + (size_t)(k0 + 2 * bq + 1) * kF + n0 + bn4 * 4);
    };
    auto stsAB = [&](int buf) {
#pragma unroll
        for (int j = 0; j < 2; j++) {
            int k4 = ak0 + j * 2;
            As2[buf][k4 * 2 + 0][am] = h2(ra[j].x, ra[j].y);
            As2[buf][k4 * 2 + 1][am] = h2(ra[j].z, ra[j].w);
        }
        uint4 bv;
        bv.x = h2(rb0.x, rb1.x); bv.y = h2(rb0.y, rb1.y);
        bv.z = h2(rb0.z, rb1.z); bv.w = h2(rb0.w, rb1.w);
        *(uint4*)&Bs2[buf][bq][bn4 * 4] = bv;
    };

    float acc[4][4][4];
#pragma unroll
    for (int i = 0; i < 4; i++)
#pragma unroll
        for (int j = 0; j < 4; j++)
#pragma unroll
            for (int q = 0; q < 4; q++) acc[i][j][q] = 0.f;

    constexpr int C = kD / BK;   // 64
    loadA(0); loadB(0);
    stsAB(0);
    __syncthreads();

    for (int c = 0; c < C; c++) {
        int cur = c & 1;
        bool more = (c + 1 < C);
        if (more) { loadA((c + 1) * BK); loadB((c + 1) * BK); }
        uint32_t af[4][4], bf[4][2];
#pragma unroll
        for (int mt = 0; mt < 4; mt++) {
            int mc = mbase + mt * 16 + grp;
            af[mt][0] = As2[cur][tig][mc];
            af[mt][1] = As2[cur][tig][mc + 8];
            af[mt][2] = As2[cur][tig + 4][mc];
            af[mt][3] = As2[cur][tig + 4][mc + 8];
        }
#pragma unroll
        for (int nt = 0; nt < 4; nt++) {
            int nc = nbase + nt * 8 + grp;
            bf[nt][0] = Bs2[cur][tig][nc];
            bf[nt][1] = Bs2[cur][tig + 4][nc];
        }
#pragma unroll
        for (int mt = 0; mt < 4; mt++)
#pragma unroll
            for (int nt = 0; nt < 4; nt++)
                mma_f16(acc[mt][nt], af[mt][0], af[mt][1], af[mt][2], af[mt][3],
                        bf[nt][0], bf[nt][1]);
        if (more) {
            stsAB(cur ^ 1);
            __syncthreads();
        }
    }

    // epilogue: bias + gelu, write fp16
    const float* bb = b1 + (size_t)e * kF + n0;
#pragma unroll
    for (int mt = 0; mt < 4; mt++) {
        int rbase = mbase + mt * 16 + grp;
#pragma unroll
        for (int h = 0; h < 2; h++) {
            int r = rbase + h * 8;
            int m = m0 + r;
            if (m < cnt) {
                __half* hrow = g_h + (size_t)(off + m) * kF + n0;
#pragma unroll
                for (int nt = 0; nt < 4; nt++) {
                    int cc = nbase + nt * 8 + tig * 2;
                    float vx = gelu_f(acc[mt][nt][h * 2 + 0] + bb[cc]);
                    float vy = gelu_f(acc[mt][nt][h * 2 + 1] + bb[cc + 1]);
                    *(uint32_t*)(hrow + cc) = h2(vx, vy);
                }
            }
        }
    }
}

// ---------------- GEMM2: out += w * (h @ W2[e] + b2) -----------------------
__global__ __launch_bounds__(256) void gemm2_tc(const float* __restrict__ W2,
                                                const float* __restrict__ b2,
                                                float* __restrict__ out) {
    int e = blockIdx.z;
    int off = g_offsets[e];
    int cnt = g_offsets[e + 1] - off;
    int m0 = blockIdx.y * BM;
    if (m0 >= cnt) return;
    int n0 = blockIdx.x * BN;

    __shared__ uint32_t As2[2][8][136];
    __shared__ uint32_t Bs2[2][8][136];
    __shared__ int   stok[BM];
    __shared__ float swt[BM];

    int tid = threadIdx.x, wid = tid >> 5, lane = tid & 31;
    int tig = lane & 3, grp = lane >> 2;
    int mbase = (wid & 1) * 64;
    int nbase = (wid >> 1) * 32;

    if (tid < BM) {
        int m = m0 + tid;
        stok[tid] = (m < cnt) ? g_tok[off + m] : -1;
        swt[tid]  = (m < cnt) ? g_wt[off + m] : 0.f;
    }
    __syncthreads();

    const float* Wb = W2 + (size_t)e * kF * kD;

    // A staging: g_h is already fp16 — straight uint4 copy (8 halves along k)
    int am  = tid & 127;
    int ak0 = tid >> 7;                 // 0 or 1 -> k offset ak0*8
    bool avalid = (m0 + am) < cnt;
    const __half* arow = g_h + (size_t)(off + m0 + am) * kF;
    int bq  = tid >> 5;
    int bn4 = tid & 31;

    uint4 raw; float4 rb0, rb1;
    auto loadA = [&](int k0) {
        raw = avalid ? *(const uint4*)(arow + k0 + ak0 * 8)
                     : make_uint4(0u, 0u, 0u, 0u);
    };
    auto loadB = [&](int k0) {
        rb0 = *(const float4*)(Wb + (size_t)(k0 + 2 * bq) * kD + n0 + bn4 * 4);
        rb1 = *(const float4*)(Wb + (size_t)(k0 + 2 * bq + 1) * kD + n0 + bn4 * 4);
    };
    auto stsAB = [&](int buf) {
        int k2b = ak0 * 4;
        As2[buf][k2b + 0][am] = raw.x;
        As2[buf][k2b + 1][am] = raw.y;
        As2[buf][k2b + 2][am] = raw.z;
        As2[buf][k2b + 3][am] = raw.w;
        uint4 bv;
        bv.x = h2(rb0.x, rb1.x); bv.y = h2(rb0.y, rb1.y);
        bv.z = h2(rb0.z, rb1.z); bv.w = h2(rb0.w, rb1.w);
        *(uint4*)&Bs2[buf][bq][bn4 * 4] = bv;
    };

    float acc[4][4][4];
#pragma unroll
    for (int i = 0; i < 4; i++)
#pragma unroll
        for (int j = 0; j < 4; j++)
#pragma unroll
            for (int q = 0; q < 4; q++) acc[i][j][q] = 0.f;

    constexpr int C = kF / BK;   // 256
    loadA(0); loadB(0);
    stsAB(0);
    __syncthreads();

    for (int c = 0; c < C; c++) {
        int cur = c & 1;
        bool more = (c + 1 < C);
        if (more) { loadA((c + 1) * BK); loadB((c + 1) * BK); }
        uint32_t af[4][4], bf[4][2];
#pragma unroll
        for (int mt = 0; mt < 4; mt++) {
            int mc = mbase + mt * 16 + grp;
            af[mt][0] = As2[cur][tig][mc];
            af[mt][1] = As2[cur][tig][mc + 8];
            af[mt][2] = As2[cur][tig + 4][mc];
            af[mt][3] = As2[cur][tig + 4][mc + 8];
        }
#pragma unroll
        for (int nt = 0; nt < 4; nt++) {
            int nc = nbase + nt * 8 + grp;
            bf[nt][0] = Bs2[cur][tig][nc];
            bf[nt][1] = Bs2[cur][tig + 4][nc];
        }
#pragma unroll
        for (int mt = 0; mt < 4; mt++)
#pragma unroll
            for (int nt = 0; nt < 4; nt++)
                mma_f16(acc[mt][nt], af[mt][0], af[mt][1], af[mt][2], af[mt][3],
                        bf[nt][0], bf[nt][1]);
        if (more) {
            stsAB(cur ^ 1);
            __syncthreads();
        }
    }

    // epilogue: weighted atomic scatter (fp32)
    const float* bbv = b2 + (size_t)e * kD + n0;
#pragma unroll
    for (int mt = 0; mt < 4; mt++) {
        int rbase = mbase + mt * 16 + grp;
#pragma unroll
        for (int h = 0; h < 2; h++) {
            int r = rbase + h * 8;
            int m = m0 + r;
            if (m < cnt) {
                int   tok = stok[r];
                float w   = swt[r];
                float* orow = out + (size_t)tok * kD + n0;
#pragma unroll
                for (int nt = 0; nt < 4; nt++) {
                    int cc = nbase + nt * 8 + tig * 2;
                    atomicAdd(&orow[cc],     w * (acc[mt][nt][h * 2 + 0] + bbv[cc]));
                    atomicAdd(&orow[cc + 1], w * (acc[mt][nt][h * 2 + 1] + bbv[cc + 1]));
                }
            }
        }
    }
}

// ---------------- launch ----------------
extern "C" void kernel_launch(void* const* d_in, const int* in_sizes, int n_in,
                              void* d_out, int out_size) {
    const float* x  = (const float*)d_in[0];
    const float* Wg = (const float*)d_in[1];
    const float* bg = (const float*)d_in[2];
    const float* W1 = (const float*)d_in[3];
    const float* b1 = (const float*)d_in[4];
    const float* W2 = (const float*)d_in[5];
    const float* b2 = (const float*)d_in[6];
    float* out = (float*)d_out;

    cudaMemsetAsync(out, 0, (size_t)out_size * sizeof(float));
    init_kernel<<<1, 32>>>();
    gate_kernel<<<kTOK / 8, 256>>>(x, Wg, bg);
    scan_kernel<<<1, 1>>>();
    scatter_kernel<<<kASSIGN / 256, 256>>>();
    gemm1_tc<<<dim3(kF / BN, kTOK / BM, kE), 256>>>(x, W1, b1);
    gemm2_tc<<<dim3(kD / BN, kTOK / BM, kE), 256>>>(W2, b2, out);
}

// round 5
// speedup vs baseline: 3.7178x; 1.1905x over previous
#include <cuda_runtime.h>
#include <cuda_fp16.h>
#include <cstdint>
#include <math.h>

// ---------------- problem constants ----------------
constexpr int kTOK = 8192;
constexpr int kD   = 1024;
constexpr int kF   = 4096;
constexpr int kE   = 8;
constexpr int kASSIGN = kTOK * 2;

constexpr int BM = 128, BN = 128, BK = 16;

// ---------------- device scratch ----------------
__device__ int   g_topk_e[kASSIGN];
__device__ float g_topk_w[kASSIGN];
__device__ int   g_counts[kE];
__device__ int   g_offsets[kE + 1];
__device__ int   g_cursors[kE];
__device__ int   g_tok[kASSIGN];
__device__ float g_wt[kASSIGN];
__device__ __half   g_h[(size_t)kASSIGN * kF];              // 134 MB fp16 activations
__device__ uint32_t g_w1h[(size_t)kE * (kD / 2) * kF];      // 67 MB fp16 W1, k2-interleaved
__device__ uint32_t g_w2h[(size_t)kE * (kF / 2) * kD];      // 67 MB fp16 W2, k2-interleaved
__device__ uint32_t g_xh[(size_t)kTOK * (kD / 2)];          // 16 MB fp16 x (pairwise)

// ---------------- helpers ----------------
__device__ __forceinline__ void mma_f16(float* c, uint32_t a0, uint32_t a1,
                                        uint32_t a2, uint32_t a3,
                                        uint32_t b0, uint32_t b1) {
    asm volatile("mma.sync.aligned.m16n8k16.row.col.f32.f16.f16.f32 "
                 "{%0,%1,%2,%3}, {%4,%5,%6,%7}, {%8,%9}, {%0,%1,%2,%3};"
                 : "+f"(c[0]), "+f"(c[1]), "+f"(c[2]), "+f"(c[3])
                 : "r"(a0), "r"(a1), "r"(a2), "r"(a3), "r"(b0), "r"(b1));
}
__device__ __forceinline__ uint32_t h2(float a, float b) {
    __half2 h = __floats2half2_rn(a, b);
    return *(uint32_t*)&h;
}
__device__ __forceinline__ float gelu_f(float v) {
    return 0.5f * v * (1.0f + erff(v * 0.70710678118654752f));
}
__device__ __forceinline__ uint32_t smem_u32(const void* p) {
    uint32_t a;
    asm("{ .reg .u64 t; cvta.to.shared.u64 t, %1; cvt.u32.u64 %0, t; }"
        : "=r"(a) : "l"(p));
    return a;
}
#define CP_ASYNC16(dst, src) \
    asm volatile("cp.async.cg.shared.global [%0], [%1], 16;" :: "r"(dst), "l"(src))
#define CP_COMMIT() asm volatile("cp.async.commit_group;" ::: "memory")
#define CP_WAIT0()  asm volatile("cp.async.wait_group 0;" ::: "memory")

// ---------------- routing kernels ----------------
__global__ void init_kernel() {
    int i = threadIdx.x;
    if (i < kE) { g_counts[i] = 0; g_cursors[i] = 0; }
}

__global__ void gate_kernel(const float* __restrict__ x, const float* __restrict__ Wg,
                            const float* __restrict__ bg) {
    int w = (blockIdx.x * blockDim.x + threadIdx.x) >> 5;
    int lane = threadIdx.x & 31;
    if (w >= kTOK) return;
    const float* xr = x + (size_t)w * kD;
    float acc[kE];
#pragma unroll
    for (int e = 0; e < kE; e++) acc[e] = 0.f;
    for (int d = lane * 4; d < kD; d += 128) {
        float4 xv = *(const float4*)(xr + d);
#pragma unroll
        for (int e = 0; e < kE; e++) {
            float4 wv = *(const float4*)(Wg + e * kD + d);
            acc[e] += xv.x * wv.x + xv.y * wv.y + xv.z * wv.z + xv.w * wv.w;
        }
    }
#pragma unroll
    for (int e = 0; e < kE; e++)
#pragma unroll
        for (int o = 16; o; o >>= 1) acc[e] += __shfl_xor_sync(0xffffffffu, acc[e], o);
    if (lane == 0) {
        float l[kE];
#pragma unroll
        for (int e = 0; e < kE; e++) l[e] = acc[e] + bg[e];
        int i1 = 0;
#pragma unroll
        for (int e = 1; e < kE; e++) if (l[e] > l[i1]) i1 = e;
        int i2 = (i1 == 0) ? 1 : 0;
#pragma unroll
        for (int e = 0; e < kE; e++) if (e != i1 && l[e] > l[i2]) i2 = e;
        float w1 = 1.f / (1.f + expf(l[i2] - l[i1]));
        g_topk_e[2 * w] = i1; g_topk_e[2 * w + 1] = i2;
        g_topk_w[2 * w] = w1; g_topk_w[2 * w + 1] = 1.f - w1;
        atomicAdd(&g_counts[i1], 1);
        atomicAdd(&g_counts[i2], 1);
    }
}

__global__ void scan_kernel() {
    int s = 0;
#pragma unroll
    for (int e = 0; e < kE; e++) { g_offsets[e] = s; s += g_counts[e]; }
    g_offsets[kE] = s;
}

__global__ void scatter_kernel() {
    int i = blockIdx.x * blockDim.x + threadIdx.x;
    if (i >= kASSIGN) return;
    int e = g_topk_e[i];
    int pos = g_offsets[e] + atomicAdd(&g_cursors[e], 1);
    g_tok[pos] = i >> 1;
    g_wt[pos] = g_topk_w[i];
}

// ---------------- conversion prologue kernels ----------------
// W1h[e][k2][n] = half2(W1[e][2k2][n], W1[e][2k2+1][n])
__global__ void convert_w1(const float* __restrict__ W1) {
    int idx = blockIdx.x * blockDim.x + threadIdx.x;      // kE*512*1024 threads
    int n4 = idx & 1023;
    int r  = idx >> 10;
    int k2 = r & 511;
    int e  = r >> 9;
    const float* base = W1 + ((size_t)e * kD + 2 * k2) * kF + n4 * 4;
    float4 a = *(const float4*)base;
    float4 b = *(const float4*)(base + kF);
    uint4 o = make_uint4(h2(a.x, b.x), h2(a.y, b.y), h2(a.z, b.z), h2(a.w, b.w));
    *(uint4*)(g_w1h + ((size_t)e * (kD / 2) + k2) * kF + n4 * 4) = o;
}
// W2h[e][k2][n] = half2(W2[e][2k2][n], W2[e][2k2+1][n])
__global__ void convert_w2(const float* __restrict__ W2) {
    int idx = blockIdx.x * blockDim.x + threadIdx.x;      // kE*2048*256 threads
    int n4 = idx & 255;
    int r  = idx >> 8;
    int k2 = r & 2047;
    int e  = r >> 11;
    const float* base = W2 + ((size_t)e * kF + 2 * k2) * kD + n4 * 4;
    float4 a = *(const float4*)base;
    float4 b = *(const float4*)(base + kD);
    uint4 o = make_uint4(h2(a.x, b.x), h2(a.y, b.y), h2(a.z, b.z), h2(a.w, b.w));
    *(uint4*)(g_w2h + ((size_t)e * (kF / 2) + k2) * kD + n4 * 4) = o;
}
// xh[tok][j] = half2(x[tok][2j], x[tok][2j+1])
__global__ void convert_x(const float* __restrict__ x) {
    int idx = blockIdx.x * blockDim.x + threadIdx.x;      // kTOK*128 threads
    const float* base = x + (size_t)idx * 8;
    float4 f0 = *(const float4*)base;
    float4 f1 = *(const float4*)(base + 4);
    uint4 o = make_uint4(h2(f0.x, f0.y), h2(f0.z, f0.w), h2(f1.x, f1.y), h2(f1.z, f1.w));
    *(uint4*)(g_xh + (size_t)idx * 4) = o;
}

// ======================= fp16 mma.sync GEMM kernels ========================
// Tile 128x128x16, 256 threads = 8 warps (2 M x 4 N), warp tile 64x32.
// As2[k2][m], Bs2[k2][n], half2-packed along K, 136-uint32 row pad.
// B staged by cp.async directly from pre-interleaved fp16 weights.

// ---------------- GEMM1: h = gelu(gather(xh) @ W1h + b1) -------------------
__global__ __launch_bounds__(256) void gemm1_tc(const float* __restrict__ b1) {
    int e = blockIdx.z;
    int off = g_offsets[e];
    int cnt = g_offsets[e + 1] - off;
    int m0 = blockIdx.y * BM;
    if (m0 >= cnt) return;
    int n0 = blockIdx.x * BN;

    __shared__ __align__(16) uint32_t As2[2][8][136];
    __shared__ __align__(16) uint32_t Bs2[2][8][136];
    __shared__ int stok[BM];

    int tid = threadIdx.x, wid = tid >> 5, lane = tid & 31;
    int tig = lane & 3, grp = lane >> 2;
    int mbase = (wid & 1) * 64;
    int nbase = (wid >> 1) * 32;

    if (tid < BM) {
        int m = m0 + tid;
        stok[tid] = (m < cnt) ? g_tok[off + m] : -1;
    }
    __syncthreads();

    // A staging: thread owns row am, 4 consecutive k2 at ak0*4
    int am  = tid & 127;
    int ak0 = tid >> 7;
    int atok = stok[am];
    const uint32_t* arow = (atok >= 0) ? g_xh + (size_t)atok * (kD / 2) : nullptr;
    // B staging: one 16B cp.async per thread: row bq, cols bn4*4..+3
    int bq  = tid >> 5;
    int bn4 = tid & 31;
    const uint32_t* bsrc = g_w1h + ((size_t)e * (kD / 2) + bq) * kF + n0 + bn4 * 4;
    uint32_t bdst[2];
    bdst[0] = smem_u32(&Bs2[0][bq][bn4 * 4]);
    bdst[1] = smem_u32(&Bs2[1][bq][bn4 * 4]);

    uint4 raw;
    auto loadA = [&](int k20) {
        raw = arow ? *(const uint4*)(arow + k20 + ak0 * 4)
                   : make_uint4(0u, 0u, 0u, 0u);
    };
    auto stsA = [&](int buf) {
        int kb = ak0 * 4;
        As2[buf][kb + 0][am] = raw.x;
        As2[buf][kb + 1][am] = raw.y;
        As2[buf][kb + 2][am] = raw.z;
        As2[buf][kb + 3][am] = raw.w;
    };
    auto copyB = [&](int buf, int k20) {
        CP_ASYNC16(bdst[buf], bsrc + (size_t)k20 * kF);
        CP_COMMIT();
    };

    float acc[4][4][4];
#pragma unroll
    for (int i = 0; i < 4; i++)
#pragma unroll
        for (int j = 0; j < 4; j++)
#pragma unroll
            for (int q = 0; q < 4; q++) acc[i][j][q] = 0.f;

    constexpr int C = kD / BK;   // 64 chunks, 8 k2-rows each
    copyB(0, 0);
    loadA(0);
    stsA(0);
    CP_WAIT0();
    __syncthreads();

    for (int c = 0; c < C; c++) {
        int cur = c & 1;
        bool more = (c + 1 < C);
        if (more) { copyB(cur ^ 1, (c + 1) * 8); loadA((c + 1) * 8); }
        uint32_t af[4][4], bf[4][2];
#pragma unroll
        for (int mt = 0; mt < 4; mt++) {
            int mc = mbase + mt * 16 + grp;
            af[mt][0] = As2[cur][tig][mc];
            af[mt][1] = As2[cur][tig][mc + 8];
            af[mt][2] = As2[cur][tig + 4][mc];
            af[mt][3] = As2[cur][tig + 4][mc + 8];
        }
#pragma unroll
        for (int nt = 0; nt < 4; nt++) {
            int nc = nbase + nt * 8 + grp;
            bf[nt][0] = Bs2[cur][tig][nc];
            bf[nt][1] = Bs2[cur][tig + 4][nc];
        }
#pragma unroll
        for (int mt = 0; mt < 4; mt++)
#pragma unroll
            for (int nt = 0; nt < 4; nt++)
                mma_f16(acc[mt][nt], af[mt][0], af[mt][1], af[mt][2], af[mt][3],
                        bf[nt][0], bf[nt][1]);
        if (more) {
            stsA(cur ^ 1);
            CP_WAIT0();
            __syncthreads();
        }
    }

    // epilogue: bias + gelu, write fp16
    const float* bb = b1 + (size_t)e * kF + n0;
#pragma unroll
    for (int mt = 0; mt < 4; mt++) {
        int rbase = mbase + mt * 16 + grp;
#pragma unroll
        for (int h = 0; h < 2; h++) {
            int r = rbase + h * 8;
            int m = m0 + r;
            if (m < cnt) {
                __half* hrow = g_h + (size_t)(off + m) * kF + n0;
#pragma unroll
                for (int nt = 0; nt < 4; nt++) {
                    int cc = nbase + nt * 8 + tig * 2;
                    float vx = gelu_f(acc[mt][nt][h * 2 + 0] + bb[cc]);
                    float vy = gelu_f(acc[mt][nt][h * 2 + 1] + bb[cc + 1]);
                    *(uint32_t*)(hrow + cc) = h2(vx, vy);
                }
            }
        }
    }
}

// ---------------- GEMM2: out += w * (h @ W2h + b2) -------------------------
__global__ __launch_bounds__(256) void gemm2_tc(const float* __restrict__ b2,
                                                float* __restrict__ out) {
    int e = blockIdx.z;
    int off = g_offsets[e];
    int cnt = g_offsets[e + 1] - off;
    int m0 = blockIdx.y * BM;
    if (m0 >= cnt) return;
    int n0 = blockIdx.x * BN;

    __shared__ __align__(16) uint32_t As2[2][8][136];
    __shared__ __align__(16) uint32_t Bs2[2][8][136];
    __shared__ int   stok[BM];
    __shared__ float swt[BM];

    int tid = threadIdx.x, wid = tid >> 5, lane = tid & 31;
    int tig = lane & 3, grp = lane >> 2;
    int mbase = (wid & 1) * 64;
    int nbase = (wid >> 1) * 32;

    if (tid < BM) {
        int m = m0 + tid;
        stok[tid] = (m < cnt) ? g_tok[off + m] : -1;
        swt[tid]  = (m < cnt) ? g_wt[off + m] : 0.f;
    }
    __syncthreads();

    int am  = tid & 127;
    int ak0 = tid >> 7;
    bool avalid = (m0 + am) < cnt;
    const __half* arow = g_h + (size_t)(off + m0 + am) * kF;
    int bq  = tid >> 5;
    int bn4 = tid & 31;
    const uint32_t* bsrc = g_w2h + ((size_t)e * (kF / 2) + bq) * kD + n0 + bn4 * 4;
    uint32_t bdst[2];
    bdst[0] = smem_u32(&Bs2[0][bq][bn4 * 4]);
    bdst[1] = smem_u32(&Bs2[1][bq][bn4 * 4]);

    uint4 raw;
    auto loadA = [&](int k0) {   // k0 in half units
        raw = avalid ? *(const uint4*)(arow + k0 + ak0 * 8)
                     : make_uint4(0u, 0u, 0u, 0u);
    };
    auto stsA = [&](int buf) {
        int kb = ak0 * 4;
        As2[buf][kb + 0][am] = raw.x;
        As2[buf][kb + 1][am] = raw.y;
        As2[buf][kb + 2][am] = raw.z;
        As2[buf][kb + 3][am] = raw.w;
    };
    auto copyB = [&](int buf, int k20) {
        CP_ASYNC16(bdst[buf], bsrc + (size_t)k20 * kD);
        CP_COMMIT();
    };

    float acc[4][4][4];
#pragma unroll
    for (int i = 0; i < 4; i++)
#pragma unroll
        for (int j = 0; j < 4; j++)
#pragma unroll
            for (int q = 0; q < 4; q++) acc[i][j][q] = 0.f;

    constexpr int C = kF / BK;   // 256 chunks
    copyB(0, 0);
    loadA(0);
    stsA(0);
    CP_WAIT0();
    __syncthreads();

    for (int c = 0; c < C; c++) {
        int cur = c & 1;
        bool more = (c + 1 < C);
        if (more) { copyB(cur ^ 1, (c + 1) * 8); loadA((c + 1) * BK); }
        uint32_t af[4][4], bf[4][2];
#pragma unroll
        for (int mt = 0; mt < 4; mt++) {
            int mc = mbase + mt * 16 + grp;
            af[mt][0] = As2[cur][tig][mc];
            af[mt][1] = As2[cur][tig][mc + 8];
            af[mt][2] = As2[cur][tig + 4][mc];
            af[mt][3] = As2[cur][tig + 4][mc + 8];
        }
#pragma unroll
        for (int nt = 0; nt < 4; nt++) {
            int nc = nbase + nt * 8 + grp;
            bf[nt][0] = Bs2[cur][tig][nc];
            bf[nt][1] = Bs2[cur][tig + 4][nc];
        }
#pragma unroll
        for (int mt = 0; mt < 4; mt++)
#pragma unroll
            for (int nt = 0; nt < 4; nt++)
                mma_f16(acc[mt][nt], af[mt][0], af[mt][1], af[mt][2], af[mt][3],
                        bf[nt][0], bf[nt][1]);
        if (more) {
            stsA(cur ^ 1);
            CP_WAIT0();
            __syncthreads();
        }
    }

    // epilogue: weighted atomic scatter (fp32)
    const float* bbv = b2 + (size_t)e * kD + n0;
#pragma unroll
    for (int mt = 0; mt < 4; mt++) {
        int rbase = mbase + mt * 16 + grp;
#pragma unroll
        for (int h = 0; h < 2; h++) {
            int r = rbase + h * 8;
            int m = m0 + r;
            if (m < cnt) {
                int   tok = stok[r];
                float w   = swt[r];
                float* orow = out + (size_t)tok * kD + n0;
#pragma unroll
                for (int nt = 0; nt < 4; nt++) {
                    int cc = nbase + nt * 8 + tig * 2;
                    atomicAdd(&orow[cc],     w * (acc[mt][nt][h * 2 + 0] + bbv[cc]));
                    atomicAdd(&orow[cc + 1], w * (acc[mt][nt][h * 2 + 1] + bbv[cc + 1]));
                }
            }
        }
    }
}

// ---------------- launch ----------------
extern "C" void kernel_launch(void* const* d_in, const int* in_sizes, int n_in,
                              void* d_out, int out_size) {
    const float* x  = (const float*)d_in[0];
    const float* Wg = (const float*)d_in[1];
    const float* bg = (const float*)d_in[2];
    const float* W1 = (const float*)d_in[3];
    const float* b1 = (const float*)d_in[4];
    const float* W2 = (const float*)d_in[5];
    const float* b2 = (const float*)d_in[6];
    float* out = (float*)d_out;

    cudaMemsetAsync(out, 0, (size_t)out_size * sizeof(float));
    init_kernel<<<1, 32>>>();
    gate_kernel<<<kTOK / 8, 256>>>(x, Wg, bg);
    convert_x<<<kTOK * (kD / 8) / 256, 256>>>(x);
    convert_w1<<<kE * (kD / 2) * (kF / 4) / 256, 256>>>(W1);
    convert_w2<<<kE * (kF / 2) * (kD / 4) / 256, 256>>>(W2);
    scan_kernel<<<1, 1>>>();
    scatter_kernel<<<kASSIGN / 256, 256>>>();
    gemm1_tc<<<dim3(kF / BN, kTOK / BM, kE), 256>>>(b1);
    gemm2_tc<<<dim3(kD / BN, kTOK / BM, kE), 256>>>(b2, out);
}

// round 6
// speedup vs baseline: 4.5926x; 1.2353x over previous
#include <cuda_runtime.h>
#include <cuda_fp16.h>
#include <cstdint>
#include <math.h>

// ---------------- problem constants ----------------
constexpr int kTOK = 8192;
constexpr int kD   = 1024;
constexpr int kF   = 4096;
constexpr int kE   = 8;
constexpr int kASSIGN = kTOK * 2;

constexpr int BM = 128, BN = 128, BK = 16;
constexpr int STG = 4;                    // cp.async ring stages
constexpr int PADA = 12;                  // uint32 per A row (48B)
constexpr int A_STAGE_U32 = BM * PADA;    // 1536 uint32 = 6144B
constexpr int B_STAGE_U32 = 8 * 136;      // 1088 uint32 = 4352B

// ---------------- device scratch ----------------
__device__ int   g_topk_e[kASSIGN];
__device__ float g_topk_w[kASSIGN];
__device__ int   g_counts[kE];
__device__ int   g_offsets[kE + 1];
__device__ int   g_cursors[kE];
__device__ int   g_tok[kASSIGN];
__device__ float g_wt[kASSIGN];
__device__ __half   g_h[(size_t)kASSIGN * kF];              // fp16 activations
__device__ uint32_t g_w1h[(size_t)kE * (kD / 2) * kF];      // fp16 W1, k2-interleaved
__device__ uint32_t g_w2h[(size_t)kE * (kF / 2) * kD];      // fp16 W2, k2-interleaved
__device__ uint32_t g_xh[(size_t)kTOK * (kD / 2)];          // fp16 x (pairwise)

// ---------------- helpers ----------------
__device__ __forceinline__ void mma_f16(float* c, uint32_t a0, uint32_t a1,
                                        uint32_t a2, uint32_t a3,
                                        uint32_t b0, uint32_t b1) {
    asm volatile("mma.sync.aligned.m16n8k16.row.col.f32.f16.f16.f32 "
                 "{%0,%1,%2,%3}, {%4,%5,%6,%7}, {%8,%9}, {%0,%1,%2,%3};"
                 : "+f"(c[0]), "+f"(c[1]), "+f"(c[2]), "+f"(c[3])
                 : "r"(a0), "r"(a1), "r"(a2), "r"(a3), "r"(b0), "r"(b1));
}
__device__ __forceinline__ void ldmatrix_x4(uint32_t* r, uint32_t addr) {
    asm volatile("ldmatrix.sync.aligned.m8n8.x4.shared.b16 {%0,%1,%2,%3}, [%4];"
                 : "=r"(r[0]), "=r"(r[1]), "=r"(r[2]), "=r"(r[3]) : "r"(addr));
}
__device__ __forceinline__ uint32_t h2(float a, float b) {
    __half2 h = __floats2half2_rn(a, b);
    return *(uint32_t*)&h;
}
__device__ __forceinline__ float gelu_f(float v) {
    return 0.5f * v * (1.0f + erff(v * 0.70710678118654752f));
}
__device__ __forceinline__ uint32_t smem_u32(const void* p) {
    uint32_t a;
    asm("{ .reg .u64 t; cvta.to.shared.u64 t, %1; cvt.u32.u64 %0, t; }"
        : "=r"(a) : "l"(p));
    return a;
}
#define CP_ASYNC16(dst, src) \
    asm volatile("cp.async.cg.shared.global [%0], [%1], 16;" :: "r"(dst), "l"(src))
#define CP_ASYNC16Z(dst, src, sz) \
    asm volatile("cp.async.cg.shared.global [%0], [%1], 16, %2;" :: "r"(dst), "l"(src), "r"(sz))
#define CP_COMMIT() asm volatile("cp.async.commit_group;" ::: "memory")
#define CP_WAIT2()  asm volatile("cp.async.wait_group 2;" ::: "memory")

// ---------------- routing kernels ----------------
__global__ void init_kernel() {
    int i = threadIdx.x;
    if (i < kE) { g_counts[i] = 0; g_cursors[i] = 0; }
}

__global__ void gate_kernel(const float* __restrict__ x, const float* __restrict__ Wg,
                            const float* __restrict__ bg) {
    int w = (blockIdx.x * blockDim.x + threadIdx.x) >> 5;
    int lane = threadIdx.x & 31;
    if (w >= kTOK) return;
    const float* xr = x + (size_t)w * kD;
    float acc[kE];
#pragma unroll
    for (int e = 0; e < kE; e++) acc[e] = 0.f;
    for (int d = lane * 4; d < kD; d += 128) {
        float4 xv = *(const float4*)(xr + d);
#pragma unroll
        for (int e = 0; e < kE; e++) {
            float4 wv = *(const float4*)(Wg + e * kD + d);
            acc[e] += xv.x * wv.x + xv.y * wv.y + xv.z * wv.z + xv.w * wv.w;
        }
    }
#pragma unroll
    for (int e = 0; e < kE; e++)
#pragma unroll
        for (int o = 16; o; o >>= 1) acc[e] += __shfl_xor_sync(0xffffffffu, acc[e], o);
    if (lane == 0) {
        float l[kE];
#pragma unroll
        for (int e = 0; e < kE; e++) l[e] = acc[e] + bg[e];
        int i1 = 0;
#pragma unroll
        for (int e = 1; e < kE; e++) if (l[e] > l[i1]) i1 = e;
        int i2 = (i1 == 0) ? 1 : 0;
#pragma unroll
        for (int e = 0; e < kE; e++) if (e != i1 && l[e] > l[i2]) i2 = e;
        float w1 = 1.f / (1.f + expf(l[i2] - l[i1]));
        g_topk_e[2 * w] = i1; g_topk_e[2 * w + 1] = i2;
        g_topk_w[2 * w] = w1; g_topk_w[2 * w + 1] = 1.f - w1;
        atomicAdd(&g_counts[i1], 1);
        atomicAdd(&g_counts[i2], 1);
    }
}

__global__ void scan_kernel() {
    int s = 0;
#pragma unroll
    for (int e = 0; e < kE; e++) { g_offsets[e] = s; s += g_counts[e]; }
    g_offsets[kE] = s;
}

__global__ void scatter_kernel() {
    int i = blockIdx.x * blockDim.x + threadIdx.x;
    if (i >= kASSIGN) return;
    int e = g_topk_e[i];
    int pos = g_offsets[e] + atomicAdd(&g_cursors[e], 1);
    g_tok[pos] = i >> 1;
    g_wt[pos] = g_topk_w[i];
}

// ---------------- conversion prologue kernels ----------------
__global__ void convert_w1(const float* __restrict__ W1) {
    int idx = blockIdx.x * blockDim.x + threadIdx.x;
    int n4 = idx & 1023;
    int r  = idx >> 10;
    int k2 = r & 511;
    int e  = r >> 9;
    const float* base = W1 + ((size_t)e * kD + 2 * k2) * kF + n4 * 4;
    float4 a = *(const float4*)base;
    float4 b = *(const float4*)(base + kF);
    uint4 o = make_uint4(h2(a.x, b.x), h2(a.y, b.y), h2(a.z, b.z), h2(a.w, b.w));
    *(uint4*)(g_w1h + ((size_t)e * (kD / 2) + k2) * kF + n4 * 4) = o;
}
__global__ void convert_w2(const float* __restrict__ W2) {
    int idx = blockIdx.x * blockDim.x + threadIdx.x;
    int n4 = idx & 255;
    int r  = idx >> 8;
    int k2 = r & 2047;
    int e  = r >> 11;
    const float* base = W2 + ((size_t)e * kF + 2 * k2) * kD + n4 * 4;
    float4 a = *(const float4*)base;
    float4 b = *(const float4*)(base + kD);
    uint4 o = make_uint4(h2(a.x, b.x), h2(a.y, b.y), h2(a.z, b.z), h2(a.w, b.w));
    *(uint4*)(g_w2h + ((size_t)e * (kF / 2) + k2) * kD + n4 * 4) = o;
}
__global__ void convert_x(const float* __restrict__ x) {
    int idx = blockIdx.x * blockDim.x + threadIdx.x;
    const float* base = x + (size_t)idx * 8;
    float4 f0 = *(const float4*)base;
    float4 f1 = *(const float4*)(base + 4);
    uint4 o = make_uint4(h2(f0.x, f0.y), h2(f0.z, f0.w), h2(f1.x, f1.y), h2(f1.z, f1.w));
    *(uint4*)(g_xh + (size_t)idx * 4) = o;
}

// ======================= fp16 mma.sync GEMM kernels ========================
// Tile 128x128x16, 8 warps (2M x 4N), warp tile 64x32.
// A smem: m-major [m][k-halves], 48B row pad -> conflict-free ldmatrix.
// B smem: [k2][n] 136-pad, conflict-free scalar LDS.
// Both staged by a 4-stage cp.async ring (wait_group 2 => 3 chunks in flight).

// ---------------- GEMM1: h = gelu(gather(xh) @ W1h + b1) -------------------
__global__ __launch_bounds__(256) void gemm1_tc(const float* __restrict__ b1) {
    int e = blockIdx.z;
    int off = g_offsets[e];
    int cnt = g_offsets[e + 1] - off;
    int m0 = blockIdx.y * BM;
    if (m0 >= cnt) return;
    int n0 = blockIdx.x * BN;

    __shared__ __align__(16) uint32_t As[STG][BM][PADA];
    __shared__ __align__(16) uint32_t Bs[STG][8][136];
    __shared__ int stok[BM];

    int tid = threadIdx.x, wid = tid >> 5, lane = tid & 31;
    int tig = lane & 3, grp = lane >> 2;
    int mbase = (wid & 1) * 64;
    int nbase = (wid >> 1) * 32;

    if (tid < BM) {
        int m = m0 + tid;
        stok[tid] = (m < cnt) ? g_tok[off + m] : -1;
    }
    __syncthreads();

    // staging geometry
    int am  = tid & 127;           // A row
    int ak0 = tid >> 7;            // 0/1: which 16B of the 32B row
    int atok = stok[am];
    const uint32_t* asrc = g_xh + (size_t)((atok >= 0) ? atok : 0) * (kD / 2) + ak0 * 4;
    uint32_t asz = (atok >= 0) ? 16u : 0u;
    uint32_t adst0 = smem_u32(&As[0][am][ak0 * 4]);
    int bq  = tid >> 5;            // B k2-row (= warp id)
    int bn4 = tid & 31;
    const uint32_t* bsrc = g_w1h + ((size_t)e * (kD / 2) + bq) * kF + n0 + bn4 * 4;
    uint32_t bdst0 = smem_u32(&Bs[0][bq][bn4 * 4]);

    auto issue = [&](int s, int c) {
        CP_ASYNC16Z(adst0 + s * (A_STAGE_U32 * 4), asrc + c * 8, asz);
        CP_ASYNC16(bdst0 + s * (B_STAGE_U32 * 4), bsrc + (size_t)c * 8 * kF);
        CP_COMMIT();
    };

    // ldmatrix addressing: lanes 0-15 -> rows base+(lane&15), kh = lane>>4
    int rowsel = lane & 15;
    int kh = lane >> 4;
    uint32_t a_lm0 = smem_u32(&As[0][mbase + rowsel][0]) + kh * 16;

    float acc[4][4][4];
#pragma unroll
    for (int i = 0; i < 4; i++)
#pragma unroll
        for (int j = 0; j < 4; j++)
#pragma unroll
            for (int q = 0; q < 4; q++) acc[i][j][q] = 0.f;

    constexpr int C = kD / BK;   // 64
    issue(0, 0); issue(1, 1); issue(2, 2);

    for (int c = 0; c < C; c++) {
        int ss = c & 3;
        CP_WAIT2();
        __syncthreads();
        if (c + 3 < C) issue((c + 3) & 3, c + 3);

        uint32_t af[4][4], bf[4][2];
        uint32_t abase = a_lm0 + ss * (A_STAGE_U32 * 4);
#pragma unroll
        for (int mt = 0; mt < 4; mt++)
            ldmatrix_x4(af[mt], abase + mt * 16 * (PADA * 4));
#pragma unroll
        for (int nt = 0; nt < 4; nt++) {
            int nc = nbase + nt * 8 + grp;
            bf[nt][0] = Bs[ss][tig][nc];
            bf[nt][1] = Bs[ss][tig + 4][nc];
        }
#pragma unroll
        for (int mt = 0; mt < 4; mt++)
#pragma unroll
            for (int nt = 0; nt < 4; nt++)
                mma_f16(acc[mt][nt], af[mt][0], af[mt][1], af[mt][2], af[mt][3],
                        bf[nt][0], bf[nt][1]);
    }

    // epilogue: bias + gelu, write fp16
    const float* bb = b1 + (size_t)e * kF + n0;
#pragma unroll
    for (int mt = 0; mt < 4; mt++) {
        int rbase = mbase + mt * 16 + grp;
#pragma unroll
        for (int h = 0; h < 2; h++) {
            int r = rbase + h * 8;
            int m = m0 + r;
            if (m < cnt) {
                __half* hrow = g_h + (size_t)(off + m) * kF + n0;
#pragma unroll
                for (int nt = 0; nt < 4; nt++) {
                    int cc = nbase + nt * 8 + tig * 2;
                    float vx = gelu_f(acc[mt][nt][h * 2 + 0] + bb[cc]);
                    float vy = gelu_f(acc[mt][nt][h * 2 + 1] + bb[cc + 1]);
                    *(uint32_t*)(hrow + cc) = h2(vx, vy);
                }
            }
        }
    }
}

// ---------------- GEMM2: out += w * (h @ W2h + b2) -------------------------
__global__ __launch_bounds__(256) void gemm2_tc(const float* __restrict__ b2,
                                                float* __restrict__ out) {
    int e = blockIdx.z;
    int off = g_offsets[e];
    int cnt = g_offsets[e + 1] - off;
    int m0 = blockIdx.y * BM;
    if (m0 >= cnt) return;
    int n0 = blockIdx.x * BN;

    __shared__ __align__(16) uint32_t As[STG][BM][PADA];
    __shared__ __align__(16) uint32_t Bs[STG][8][136];
    __shared__ int   stok[BM];
    __shared__ float swt[BM];

    int tid = threadIdx.x, wid = tid >> 5, lane = tid & 31;
    int tig = lane & 3, grp = lane >> 2;
    int mbase = (wid & 1) * 64;
    int nbase = (wid >> 1) * 32;

    if (tid < BM) {
        int m = m0 + tid;
        stok[tid] = (m < cnt) ? g_tok[off + m] : -1;
        swt[tid]  = (m < cnt) ? g_wt[off + m] : 0.f;
    }
    __syncthreads();

    int am  = tid & 127;
    int ak0 = tid >> 7;
    bool avalid = (m0 + am) < cnt;
    const __half* asrc = g_h + (avalid ? (size_t)(off + m0 + am) * kF : 0) + ak0 * 8;
    uint32_t asz = avalid ? 16u : 0u;
    uint32_t adst0 = smem_u32(&As[0][am][ak0 * 4]);
    int bq  = tid >> 5;
    int bn4 = tid & 31;
    const uint32_t* bsrc = g_w2h + ((size_t)e * (kF / 2) + bq) * kD + n0 + bn4 * 4;
    uint32_t bdst0 = smem_u32(&Bs[0][bq][bn4 * 4]);

    auto issue = [&](int s, int c) {
        CP_ASYNC16Z(adst0 + s * (A_STAGE_U32 * 4), asrc + c * BK, asz);
        CP_ASYNC16(bdst0 + s * (B_STAGE_U32 * 4), bsrc + (size_t)c * 8 * kD);
        CP_COMMIT();
    };

    int rowsel = lane & 15;
    int kh = lane >> 4;
    uint32_t a_lm0 = smem_u32(&As[0][mbase + rowsel][0]) + kh * 16;

    float acc[4][4][4];
#pragma unroll
    for (int i = 0; i < 4; i++)
#pragma unroll
        for (int j = 0; j < 4; j++)
#pragma unroll
            for (int q = 0; q < 4; q++) acc[i][j][q] = 0.f;

    constexpr int C = kF / BK;   // 256
    issue(0, 0); issue(1, 1); issue(2, 2);

    for (int c = 0; c < C; c++) {
        int ss = c & 3;
        CP_WAIT2();
        __syncthreads();
        if (c + 3 < C) issue((c + 3) & 3, c + 3);

        uint32_t af[4][4], bf[4][2];
        uint32_t abase = a_lm0 + ss * (A_STAGE_U32 * 4);
#pragma unroll
        for (int mt = 0; mt < 4; mt++)
            ldmatrix_x4(af[mt], abase + mt * 16 * (PADA * 4));
#pragma unroll
        for (int nt = 0; nt < 4; nt++) {
            int nc = nbase + nt * 8 + grp;
            bf[nt][0] = Bs[ss][tig][nc];
            bf[nt][1] = Bs[ss][tig + 4][nc];
        }
#pragma unroll
        for (int mt = 0; mt < 4; mt++)
#pragma unroll
            for (int nt = 0; nt < 4; nt++)
                mma_f16(acc[mt][nt], af[mt][0], af[mt][1], af[mt][2], af[mt][3],
                        bf[nt][0], bf[nt][1]);
    }

    // epilogue: weighted atomic scatter (fp32)
    const float* bbv = b2 + (size_t)e * kD + n0;
#pragma unroll
    for (int mt = 0; mt < 4; mt++) {
        int rbase = mbase + mt * 16 + grp;
#pragma unroll
        for (int h = 0; h < 2; h++) {
            int r = rbase + h * 8;
            int m = m0 + r;
            if (m < cnt) {
                int   tok = stok[r];
                float w   = swt[r];
                float* orow = out + (size_t)tok * kD + n0;
#pragma unroll
                for (int nt = 0; nt < 4; nt++) {
                    int cc = nbase + nt * 8 + tig * 2;
                    atomicAdd(&orow[cc],     w * (acc[mt][nt][h * 2 + 0] + bbv[cc]));
                    atomicAdd(&orow[cc + 1], w * (acc[mt][nt][h * 2 + 1] + bbv[cc + 1]));
                }
            }
        }
    }
}

// ---------------- launch ----------------
extern "C" void kernel_launch(void* const* d_in, const int* in_sizes, int n_in,
                              void* d_out, int out_size) {
    const float* x  = (const float*)d_in[0];
    const float* Wg = (const float*)d_in[1];
    const float* bg = (const float*)d_in[2];
    const float* W1 = (const float*)d_in[3];
    const float* b1 = (const float*)d_in[4];
    const float* W2 = (const float*)d_in[5];
    const float* b2 = (const float*)d_in[6];
    float* out = (float*)d_out;

    cudaMemsetAsync(out, 0, (size_t)out_size * sizeof(float));
    init_kernel<<<1, 32>>>();
    gate_kernel<<<kTOK / 8, 256>>>(x, Wg, bg);
    convert_x<<<kTOK * (kD / 8) / 256, 256>>>(x);
    convert_w1<<<kE * (kD / 2) * (kF / 4) / 256, 256>>>(W1);
    convert_w2<<<kE * (kF / 2) * (kD / 4) / 256, 256>>>(W2);
    scan_kernel<<<1, 1>>>();
    scatter_kernel<<<kASSIGN / 256, 256>>>();
    gemm1_tc<<<dim3(kF / BN, kTOK / BM, kE), 256>>>(b1);
    gemm2_tc<<<dim3(kD / BN, kTOK / BM, kE), 256>>>(b2, out);
}

// round 7
// speedup vs baseline: 4.6265x; 1.0074x over previous
#include <cuda_runtime.h>
#include <cuda_fp16.h>
#include <cstdint>
#include <math.h>

// ---------------- problem constants ----------------
constexpr int kTOK = 8192;
constexpr int kD   = 1024;
constexpr int kF   = 4096;
constexpr int kE   = 8;
constexpr int kASSIGN = kTOK * 2;

constexpr int BM = 128, BN = 128;
constexpr int BK2 = 32;                    // K per pipeline stage (2 MMA phases)
constexpr int STG = 3;                     // cp.async ring stages
// per-stage smem: A = 128 rows x 80B (20 u32, conflict-free ldmatrix), B = 16 k2-rows x 544B
constexpr int A_STAGE_BYTES = BM * 80;            // 10240
constexpr int B_STAGE_BYTES = 16 * 544;           // 8704
constexpr int STAGE_BYTES   = A_STAGE_BYTES + B_STAGE_BYTES;   // 18944
constexpr int SMEM_BYTES    = STG * STAGE_BYTES;               // 56832

// ---------------- device scratch ----------------
__device__ int   g_topk_e[kASSIGN];
__device__ float g_topk_w[kASSIGN];
__device__ int   g_counts[kE];
__device__ int   g_offsets[kE + 1];
__device__ int   g_cursors[kE];
__device__ int   g_tok[kASSIGN];
__device__ float g_wt[kASSIGN];
__device__ __half   g_h[(size_t)kASSIGN * kF];              // fp16 activations
__device__ uint32_t g_w1h[(size_t)kE * (kD / 2) * kF];      // fp16 W1, k2-interleaved
__device__ uint32_t g_w2h[(size_t)kE * (kF / 2) * kD];      // fp16 W2, k2-interleaved
__device__ uint32_t g_xh[(size_t)kTOK * (kD / 2)];          // fp16 x (pairwise)

// ---------------- helpers ----------------
__device__ __forceinline__ void mma_f16(float* c, uint32_t a0, uint32_t a1,
                                        uint32_t a2, uint32_t a3,
                                        uint32_t b0, uint32_t b1) {
    asm volatile("mma.sync.aligned.m16n8k16.row.col.f32.f16.f16.f32 "
                 "{%0,%1,%2,%3}, {%4,%5,%6,%7}, {%8,%9}, {%0,%1,%2,%3};"
                 : "+f"(c[0]), "+f"(c[1]), "+f"(c[2]), "+f"(c[3])
                 : "r"(a0), "r"(a1), "r"(a2), "r"(a3), "r"(b0), "r"(b1));
}
__device__ __forceinline__ void ldmatrix_x4(uint32_t* r, uint32_t addr) {
    asm volatile("ldmatrix.sync.aligned.m8n8.x4.shared.b16 {%0,%1,%2,%3}, [%4];"
                 : "=r"(r[0]), "=r"(r[1]), "=r"(r[2]), "=r"(r[3]) : "r"(addr));
}
__device__ __forceinline__ uint32_t h2(float a, float b) {
    __half2 h = __floats2half2_rn(a, b);
    return *(uint32_t*)&h;
}
__device__ __forceinline__ float gelu_f(float v) {
    return 0.5f * v * (1.0f + erff(v * 0.70710678118654752f));
}
__device__ __forceinline__ uint32_t smem_u32(const void* p) {
    uint32_t a;
    asm("{ .reg .u64 t; cvta.to.shared.u64 t, %1; cvt.u32.u64 %0, t; }"
        : "=r"(a) : "l"(p));
    return a;
}
#define CP_ASYNC16(dst, src) \
    asm volatile("cp.async.cg.shared.global [%0], [%1], 16;" :: "r"(dst), "l"(src))
#define CP_ASYNC16Z(dst, src, sz) \
    asm volatile("cp.async.cg.shared.global [%0], [%1], 16, %2;" :: "r"(dst), "l"(src), "r"(sz))
#define CP_COMMIT() asm volatile("cp.async.commit_group;" ::: "memory")
#define CP_WAIT1()  asm volatile("cp.async.wait_group 1;" ::: "memory")

// ---------------- routing kernels ----------------
__global__ void init_kernel() {
    int i = threadIdx.x;
    if (i < kE) { g_counts[i] = 0; g_cursors[i] = 0; }
}

__global__ void gate_kernel(const float* __restrict__ x, const float* __restrict__ Wg,
                            const float* __restrict__ bg) {
    int w = (blockIdx.x * blockDim.x + threadIdx.x) >> 5;
    int lane = threadIdx.x & 31;
    if (w >= kTOK) return;
    const float* xr = x + (size_t)w * kD;
    float acc[kE];
#pragma unroll
    for (int e = 0; e < kE; e++) acc[e] = 0.f;
    for (int d = lane * 4; d < kD; d += 128) {
        float4 xv = *(const float4*)(xr + d);
#pragma unroll
        for (int e = 0; e < kE; e++) {
            float4 wv = *(const float4*)(Wg + e * kD + d);
            acc[e] += xv.x * wv.x + xv.y * wv.y + xv.z * wv.z + xv.w * wv.w;
        }
    }
#pragma unroll
    for (int e = 0; e < kE; e++)
#pragma unroll
        for (int o = 16; o; o >>= 1) acc[e] += __shfl_xor_sync(0xffffffffu, acc[e], o);
    if (lane == 0) {
        float l[kE];
#pragma unroll
        for (int e = 0; e < kE; e++) l[e] = acc[e] + bg[e];
        int i1 = 0;
#pragma unroll
        for (int e = 1; e < kE; e++) if (l[e] > l[i1]) i1 = e;
        int i2 = (i1 == 0) ? 1 : 0;
#pragma unroll
        for (int e = 0; e < kE; e++) if (e != i1 && l[e] > l[i2]) i2 = e;
        float w1 = 1.f / (1.f + expf(l[i2] - l[i1]));
        g_topk_e[2 * w] = i1; g_topk_e[2 * w + 1] = i2;
        g_topk_w[2 * w] = w1; g_topk_w[2 * w + 1] = 1.f - w1;
        atomicAdd(&g_counts[i1], 1);
        atomicAdd(&g_counts[i2], 1);
    }
}

__global__ void scan_kernel() {
    int s = 0;
#pragma unroll
    for (int e = 0; e < kE; e++) { g_offsets[e] = s; s += g_counts[e]; }
    g_offsets[kE] = s;
}

__global__ void scatter_kernel() {
    int i = blockIdx.x * blockDim.x + threadIdx.x;
    if (i >= kASSIGN) return;
    int e = g_topk_e[i];
    int pos = g_offsets[e] + atomicAdd(&g_cursors[e], 1);
    g_tok[pos] = i >> 1;
    g_wt[pos] = g_topk_w[i];
}

// ---------------- conversion prologue kernels ----------------
__global__ void convert_w1(const float* __restrict__ W1) {
    int idx = blockIdx.x * blockDim.x + threadIdx.x;
    int n4 = idx & 1023;
    int r  = idx >> 10;
    int k2 = r & 511;
    int e  = r >> 9;
    const float* base = W1 + ((size_t)e * kD + 2 * k2) * kF + n4 * 4;
    float4 a = *(const float4*)base;
    float4 b = *(const float4*)(base + kF);
    uint4 o = make_uint4(h2(a.x, b.x), h2(a.y, b.y), h2(a.z, b.z), h2(a.w, b.w));
    *(uint4*)(g_w1h + ((size_t)e * (kD / 2) + k2) * kF + n4 * 4) = o;
}
__global__ void convert_w2(const float* __restrict__ W2) {
    int idx = blockIdx.x * blockDim.x + threadIdx.x;
    int n4 = idx & 255;
    int r  = idx >> 8;
    int k2 = r & 2047;
    int e  = r >> 11;
    const float* base = W2 + ((size_t)e * kF + 2 * k2) * kD + n4 * 4;
    float4 a = *(const float4*)base;
    float4 b = *(const float4*)(base + kD);
    uint4 o = make_uint4(h2(a.x, b.x), h2(a.y, b.y), h2(a.z, b.z), h2(a.w, b.w));
    *(uint4*)(g_w2h + ((size_t)e * (kF / 2) + k2) * kD + n4 * 4) = o;
}
__global__ void convert_x(const float* __restrict__ x) {
    int idx = blockIdx.x * blockDim.x + threadIdx.x;
    const float* base = x + (size_t)idx * 8;
    float4 f0 = *(const float4*)base;
    float4 f1 = *(const float4*)(base + 4);
    uint4 o = make_uint4(h2(f0.x, f0.y), h2(f0.z, f0.w), h2(f1.x, f1.y), h2(f1.z, f1.w));
    *(uint4*)(g_xh + (size_t)idx * 4) = o;
}

// ======================= fp16 mma.sync GEMM kernels ========================
// Tile 128x128, stage = 32 K (two 16-K MMA phases per sync).
// 3-stage cp.async ring in dynamic smem; wait_group 1 => 2 stages in flight.
// A smem rows 80B (20 u32) -> ldmatrix conflict-free; B rows 544B (136 u32).

// ---------------- GEMM1: h = gelu(gather(xh) @ W1h + b1) -------------------
__global__ __launch_bounds__(256, 2) void gemm1_tc(const float* __restrict__ b1) {
    int e = blockIdx.z;
    int off = g_offsets[e];
    int cnt = g_offsets[e + 1] - off;
    int m0 = blockIdx.y * BM;
    if (m0 >= cnt) return;
    int n0 = blockIdx.x * BN;

    extern __shared__ __align__(16) char dsm[];
    uint32_t sb = smem_u32(dsm);
    __shared__ int stok[BM];

    int tid = threadIdx.x, wid = tid >> 5, lane = tid & 31;
    int tig = lane & 3, grp = lane >> 2;
    int mbase = (wid & 1) * 64;
    int nbase = (wid >> 1) * 32;

    if (tid < BM) {
        int m = m0 + tid;
        stok[tid] = (m < cnt) ? g_tok[off + m] : -1;
    }
    __syncthreads();

    // A staging: row am, thread t=tid>>7 copies 16B segs 2t, 2t+1 of the 64B row
    int am = tid & 127;
    int t  = tid >> 7;
    int atok = stok[am];
    const uint32_t* asrc = g_xh + (size_t)((atok >= 0) ? atok : 0) * (kD / 2) + t * 8;
    uint32_t asz = (atok >= 0) ? 16u : 0u;
    uint32_t adst = sb + am * 80 + t * 32;
    // B staging: k2-row br (0..15), 16B segs bj and bj+16
    int br = tid >> 4;
    int bj = tid & 15;
    const uint32_t* bsrc = g_w1h + ((size_t)e * (kD / 2) + br) * kF + n0 + bj * 4;
    uint32_t bdst = sb + A_STAGE_BYTES + br * 544 + bj * 16;

    auto issue = [&](int st, int c) {
        uint32_t so = st * STAGE_BYTES;
        const uint32_t* as_ = asrc + c * 16;
        CP_ASYNC16Z(adst + so,      as_,     asz);
        CP_ASYNC16Z(adst + so + 16, as_ + 4, asz);
        const uint32_t* bs_ = bsrc + (size_t)c * 16 * kF;
        CP_ASYNC16(bdst + so,       bs_);
        CP_ASYNC16(bdst + so + 256, bs_ + 64);
        CP_COMMIT();
    };

    int rowsel = lane & 15;
    int kh = lane >> 4;
    uint32_t a_lm0 = sb + (mbase + rowsel) * 80 + kh * 16;

    float acc[4][4][4];
#pragma unroll
    for (int i = 0; i < 4; i++)
#pragma unroll
        for (int j = 0; j < 4; j++)
#pragma unroll
            for (int q = 0; q < 4; q++) acc[i][j][q] = 0.f;

    constexpr int C2 = kD / BK2;   // 32 pairs
    issue(0, 0); issue(1, 1);

    for (int c = 0; c < C2; c++) {
        int st = c % STG;
        CP_WAIT1();
        __syncthreads();
        if (c + 2 < C2) issue((c + 2) % STG, c + 2);

        uint32_t so = st * STAGE_BYTES;
        const uint32_t* Bst = (const uint32_t*)(dsm + so + A_STAGE_BYTES);
#pragma unroll
        for (int p = 0; p < 2; p++) {
            uint32_t af[4][4], bf[4][2];
            uint32_t ab = a_lm0 + so + p * 32;
#pragma unroll
            for (int mt = 0; mt < 4; mt++)
                ldmatrix_x4(af[mt], ab + mt * 16 * 80);
#pragma unroll
            for (int nt = 0; nt < 4; nt++) {
                int nc = nbase + nt * 8 + grp;
                bf[nt][0] = Bst[(p * 8 + tig) * 136 + nc];
                bf[nt][1] = Bst[(p * 8 + tig + 4) * 136 + nc];
            }
#pragma unroll
            for (int mt = 0; mt < 4; mt++)
#pragma unroll
                for (int nt = 0; nt < 4; nt++)
                    mma_f16(acc[mt][nt], af[mt][0], af[mt][1], af[mt][2], af[mt][3],
                            bf[nt][0], bf[nt][1]);
        }
    }

    // epilogue: bias + gelu, write fp16
    const float* bb = b1 + (size_t)e * kF + n0;
#pragma unroll
    for (int mt = 0; mt < 4; mt++) {
        int rbase = mbase + mt * 16 + grp;
#pragma unroll
        for (int h = 0; h < 2; h++) {
            int r = rbase + h * 8;
            int m = m0 + r;
            if (m < cnt) {
                __half* hrow = g_h + (size_t)(off + m) * kF + n0;
#pragma unroll
                for (int nt = 0; nt < 4; nt++) {
                    int cc = nbase + nt * 8 + tig * 2;
                    float vx = gelu_f(acc[mt][nt][h * 2 + 0] + bb[cc]);
                    float vy = gelu_f(acc[mt][nt][h * 2 + 1] + bb[cc + 1]);
                    *(uint32_t*)(hrow + cc) = h2(vx, vy);
                }
            }
        }
    }
}

// ---------------- GEMM2: out += w * (h @ W2h + b2) -------------------------
__global__ __launch_bounds__(256, 2) void gemm2_tc(const float* __restrict__ b2,
                                                   float* __restrict__ out) {
    int e = blockIdx.z;
    int off = g_offsets[e];
    int cnt = g_offsets[e + 1] - off;
    int m0 = blockIdx.y * BM;
    if (m0 >= cnt) return;
    int n0 = blockIdx.x * BN;

    extern __shared__ __align__(16) char dsm[];
    uint32_t sb = smem_u32(dsm);
    __shared__ int   stok[BM];
    __shared__ float swt[BM];

    int tid = threadIdx.x, wid = tid >> 5, lane = tid & 31;
    int tig = lane & 3, grp = lane >> 2;
    int mbase = (wid & 1) * 64;
    int nbase = (wid >> 1) * 32;

    if (tid < BM) {
        int m = m0 + tid;
        stok[tid] = (m < cnt) ? g_tok[off + m] : -1;
        swt[tid]  = (m < cnt) ? g_wt[off + m] : 0.f;
    }
    __syncthreads();

    int am = tid & 127;
    int t  = tid >> 7;
    bool avalid = (m0 + am) < cnt;
    const __half* asrc = g_h + (avalid ? (size_t)(off + m0 + am) * kF : 0) + t * 16;
    uint32_t asz = avalid ? 16u : 0u;
    uint32_t adst = sb + am * 80 + t * 32;
    int br = tid >> 4;
    int bj = tid & 15;
    const uint32_t* bsrc = g_w2h + ((size_t)e * (kF / 2) + br) * kD + n0 + bj * 4;
    uint32_t bdst = sb + A_STAGE_BYTES + br * 544 + bj * 16;

    auto issue = [&](int st, int c) {
        uint32_t so = st * STAGE_BYTES;
        const __half* as_ = asrc + c * 32;
        CP_ASYNC16Z(adst + so,      as_,     asz);
        CP_ASYNC16Z(adst + so + 16, as_ + 8, asz);
        const uint32_t* bs_ = bsrc + (size_t)c * 16 * kD;
        CP_ASYNC16(bdst + so,       bs_);
        CP_ASYNC16(bdst + so + 256, bs_ + 64);
        CP_COMMIT();
    };

    int rowsel = lane & 15;
    int kh = lane >> 4;
    uint32_t a_lm0 = sb + (mbase + rowsel) * 80 + kh * 16;

    float acc[4][4][4];
#pragma unroll
    for (int i = 0; i < 4; i++)
#pragma unroll
        for (int j = 0; j < 4; j++)
#pragma unroll
            for (int q = 0; q < 4; q++) acc[i][j][q] = 0.f;

    constexpr int C2 = kF / BK2;   // 128 pairs
    issue(0, 0); issue(1, 1);

    for (int c = 0; c < C2; c++) {
        int st = c % STG;
        CP_WAIT1();
        __syncthreads();
        if (c + 2 < C2) issue((c + 2) % STG, c + 2);

        uint32_t so = st * STAGE_BYTES;
        const uint32_t* Bst = (const uint32_t*)(dsm + so + A_STAGE_BYTES);
#pragma unroll
        for (int p = 0; p < 2; p++) {
            uint32_t af[4][4], bf[4][2];
            uint32_t ab = a_lm0 + so + p * 32;
#pragma unroll
            for (int mt = 0; mt < 4; mt++)
                ldmatrix_x4(af[mt], ab + mt * 16 * 80);
#pragma unroll
            for (int nt = 0; nt < 4; nt++) {
                int nc = nbase + nt * 8 + grp;
                bf[nt][0] = Bst[(p * 8 + tig) * 136 + nc];
                bf[nt][1] = Bst[(p * 8 + tig + 4) * 136 + nc];
            }
#pragma unroll
            for (int mt = 0; mt < 4; mt++)
#pragma unroll
                for (int nt = 0; nt < 4; nt++)
                    mma_f16(acc[mt][nt], af[mt][0], af[mt][1], af[mt][2], af[mt][3],
                            bf[nt][0], bf[nt][1]);
        }
    }

    // epilogue: weighted atomic scatter (fp32)
    const float* bbv = b2 + (size_t)e * kD + n0;
#pragma unroll
    for (int mt = 0; mt < 4; mt++) {
        int rbase = mbase + mt * 16 + grp;
#pragma unroll
        for (int h = 0; h < 2; h++) {
            int r = rbase + h * 8;
            int m = m0 + r;
            if (m < cnt) {
                int   tok = stok[r];
                float w   = swt[r];
                float* orow = out + (size_t)tok * kD + n0;
#pragma unroll
                for (int nt = 0; nt < 4; nt++) {
                    int cc = nbase + nt * 8 + tig * 2;
                    atomicAdd(&orow[cc],     w * (acc[mt][nt][h * 2 + 0] + bbv[cc]));
                    atomicAdd(&orow[cc + 1], w * (acc[mt][nt][h * 2 + 1] + bbv[cc + 1]));
                }
            }
        }
    }
}

// ---------------- launch ----------------
extern "C" void kernel_launch(void* const* d_in, const int* in_sizes, int n_in,
                              void* d_out, int out_size) {
    const float* x  = (const float*)d_in[0];
    const float* Wg = (const float*)d_in[1];
    const float* bg = (const float*)d_in[2];
    const float* W1 = (const float*)d_in[3];
    const float* b1 = (const float*)d_in[4];
    const float* W2 = (const float*)d_in[5];
    const float* b2 = (const float*)d_in[6];
    float* out = (float*)d_out;

    cudaFuncSetAttribute(gemm1_tc, cudaFuncAttributeMaxDynamicSharedMemorySize, SMEM_BYTES);
    cudaFuncSetAttribute(gemm2_tc, cudaFuncAttributeMaxDynamicSharedMemorySize, SMEM_BYTES);

    cudaMemsetAsync(out, 0, (size_t)out_size * sizeof(float));
    init_kernel<<<1, 32>>>();
    gate_kernel<<<kTOK / 8, 256>>>(x, Wg, bg);
    convert_x<<<kTOK * (kD / 8) / 256, 256>>>(x);
    convert_w1<<<kE * (kD / 2) * (kF / 4) / 256, 256>>>(W1);
    convert_w2<<<kE * (kF / 2) * (kD / 4) / 256, 256>>>(W2);
    scan_kernel<<<1, 1>>>();
    scatter_kernel<<<kASSIGN / 256, 256>>>();
    gemm1_tc<<<dim3(kF / BN, kTOK / BM, kE), 256, SMEM_BYTES>>>(b1);
    gemm2_tc<<<dim3(kD / BN, kTOK / BM, kE), 256, SMEM_BYTES>>>(b2, out);
}

// round 9
// speedup vs baseline: 4.6961x; 1.0150x over previous
#include <cuda_runtime.h>
#include <cuda_fp16.h>
#include <cstdint>
#include <math.h>

// ---------------- problem constants ----------------
constexpr int kTOK = 8192;
constexpr int kD   = 1024;
constexpr int kF   = 4096;
constexpr int kE   = 8;
constexpr int kASSIGN = kTOK * 2;

constexpr int BM = 128, BN = 256;
constexpr int BK2 = 32;                    // K per pipeline stage (2 MMA phases)
constexpr int STG = 3;
constexpr int A_STAGE_BYTES = BM * 80;             // 10240
constexpr int B_ROW_U32     = 264;
constexpr int B_STAGE_BYTES = 16 * B_ROW_U32 * 4;  // 16896
constexpr int STAGE_BYTES   = A_STAGE_BYTES + B_STAGE_BYTES;   // 27136
constexpr int SMEM_BYTES    = STG * STAGE_BYTES;               // 81408

// ---------------- device scratch ----------------
__device__ int   g_topk_e[kASSIGN];
__device__ float g_topk_w[kASSIGN];
__device__ int   g_counts[kE];
__device__ int   g_offsets[kE + 1];
__device__ int   g_cursors[kE];
__device__ int   g_tok[kASSIGN];
__device__ float g_wt[kASSIGN];
__device__ __half   g_h[(size_t)kASSIGN * kF];
__device__ uint32_t g_w1h[(size_t)kE * (kD / 2) * kF];
__device__ uint32_t g_w2h[(size_t)kE * (kF / 2) * kD];
__device__ uint32_t g_xh[(size_t)kTOK * (kD / 2)];

// ---------------- helpers ----------------
__device__ __forceinline__ void mma_f16(float* c, uint32_t a0, uint32_t a1,
                                        uint32_t a2, uint32_t a3,
                                        uint32_t b0, uint32_t b1) {
    asm volatile("mma.sync.aligned.m16n8k16.row.col.f32.f16.f16.f32 "
                 "{%0,%1,%2,%3}, {%4,%5,%6,%7}, {%8,%9}, {%0,%1,%2,%3};"
                 : "+f"(c[0]), "+f"(c[1]), "+f"(c[2]), "+f"(c[3])
                 : "r"(a0), "r"(a1), "r"(a2), "r"(a3), "r"(b0), "r"(b1));
}
__device__ __forceinline__ void ldmatrix_x4(uint32_t* r, uint32_t addr) {
    asm volatile("ldmatrix.sync.aligned.m8n8.x4.shared.b16 {%0,%1,%2,%3}, [%4];"
                 : "=r"(r[0]), "=r"(r[1]), "=r"(r[2]), "=r"(r[3]) : "r"(addr));
}
__device__ __forceinline__ uint32_t h2(float a, float b) {
    __half2 h = __floats2half2_rn(a, b);
    return *(uint32_t*)&h;
}
__device__ __forceinline__ float gelu_f(float v) {
    return 0.5f * v * (1.0f + erff(v * 0.70710678118654752f));
}
__device__ __forceinline__ uint32_t smem_u32(const void* p) {
    uint32_t a;
    asm("{ .reg .u64 t; cvta.to.shared.u64 t, %1; cvt.u32.u64 %0, t; }"
        : "=r"(a) : "l"(p));
    return a;
}
#define CP_ASYNC16(dst, src) \
    asm volatile("cp.async.cg.shared.global [%0], [%1], 16;" :: "r"(dst), "l"(src))
#define CP_ASYNC16Z(dst, src, sz) \
    asm volatile("cp.async.cg.shared.global [%0], [%1], 16, %2;" :: "r"(dst), "l"(src), "r"(sz))
#define CP_COMMIT() asm volatile("cp.async.commit_group;" ::: "memory")
#define CP_WAIT1()  asm volatile("cp.async.wait_group 1;" ::: "memory")
#define CP_WAIT0()  asm volatile("cp.async.wait_group 0;" ::: "memory")

// ---------------- routing kernels ----------------
__global__ void init_kernel() {
    int i = threadIdx.x;
    if (i < kE) { g_counts[i] = 0; g_cursors[i] = 0; }
}

__global__ void gate_kernel(const float* __restrict__ x, const float* __restrict__ Wg,
                            const float* __restrict__ bg) {
    int w = (blockIdx.x * blockDim.x + threadIdx.x) >> 5;
    int lane = threadIdx.x & 31;
    if (w >= kTOK) return;
    const float* xr = x + (size_t)w * kD;
    float acc[kE];
#pragma unroll
    for (int e = 0; e < kE; e++) acc[e] = 0.f;
    for (int d = lane * 4; d < kD; d += 128) {
        float4 xv = *(const float4*)(xr + d);
#pragma unroll
        for (int e = 0; e < kE; e++) {
            float4 wv = *(const float4*)(Wg + e * kD + d);
            acc[e] += xv.x * wv.x + xv.y * wv.y + xv.z * wv.z + xv.w * wv.w;
        }
    }
#pragma unroll
    for (int e = 0; e < kE; e++)
#pragma unroll
        for (int o = 16; o; o >>= 1) acc[e] += __shfl_xor_sync(0xffffffffu, acc[e], o);
    if (lane == 0) {
        float l[kE];
#pragma unroll
        for (int e = 0; e < kE; e++) l[e] = acc[e] + bg[e];
        int i1 = 0;
#pragma unroll
        for (int e = 1; e < kE; e++) if (l[e] > l[i1]) i1 = e;
        int i2 = (i1 == 0) ? 1 : 0;
#pragma unroll
        for (int e = 0; e < kE; e++) if (e != i1 && l[e] > l[i2]) i2 = e;
        float w1 = 1.f / (1.f + expf(l[i2] - l[i1]));
        g_topk_e[2 * w] = i1; g_topk_e[2 * w + 1] = i2;
        g_topk_w[2 * w] = w1; g_topk_w[2 * w + 1] = 1.f - w1;
        atomicAdd(&g_counts[i1], 1);
        atomicAdd(&g_counts[i2], 1);
    }
}

__global__ void scan_kernel() {
    int s = 0;
#pragma unroll
    for (int e = 0; e < kE; e++) { g_offsets[e] = s; s += g_counts[e]; }
    g_offsets[kE] = s;
}

__global__ void scatter_kernel() {
    int i = blockIdx.x * blockDim.x + threadIdx.x;
    if (i >= kASSIGN) return;
    int e = g_topk_e[i];
    int pos = g_offsets[e] + atomicAdd(&g_cursors[e], 1);
    g_tok[pos] = i >> 1;
    g_wt[pos] = g_topk_w[i];
}

// ---------------- conversion prologue kernels ----------------
__global__ void convert_w1(const float* __restrict__ W1) {
    int idx = blockIdx.x * blockDim.x + threadIdx.x;
    int n4 = idx & 1023;
    int r  = idx >> 10;
    int k2 = r & 511;
    int e  = r >> 9;
    const float* base = W1 + ((size_t)e * kD + 2 * k2) * kF + n4 * 4;
    float4 a = *(const float4*)base;
    float4 b = *(const float4*)(base + kF);
    uint4 o = make_uint4(h2(a.x, b.x), h2(a.y, b.y), h2(a.z, b.z), h2(a.w, b.w));
    *(uint4*)(g_w1h + ((size_t)e * (kD / 2) + k2) * kF + n4 * 4) = o;
}
__global__ void convert_w2(const float* __restrict__ W2) {
    int idx = blockIdx.x * blockDim.x + threadIdx.x;
    int n4 = idx & 255;
    int r  = idx >> 8;
    int k2 = r & 2047;
    int e  = r >> 11;
    const float* base = W2 + ((size_t)e * kF + 2 * k2) * kD + n4 * 4;
    float4 a = *(const float4*)base;
    float4 b = *(const float4*)(base + kD);
    uint4 o = make_uint4(h2(a.x, b.x), h2(a.y, b.y), h2(a.z, b.z), h2(a.w, b.w));
    *(uint4*)(g_w2h + ((size_t)e * (kF / 2) + k2) * kD + n4 * 4) = o;
}
__global__ void convert_x(const float* __restrict__ x) {
    int idx = blockIdx.x * blockDim.x + threadIdx.x;
    const float* base = x + (size_t)idx * 8;
    float4 f0 = *(const float4*)base;
    float4 f1 = *(const float4*)(base + 4);
    uint4 o = make_uint4(h2(f0.x, f0.y), h2(f0.z, f0.w), h2(f1.x, f1.y), h2(f1.z, f1.w));
    *(uint4*)(g_xh + (size_t)idx * 4) = o;
}

// ======================= fp16 mma.sync GEMM kernels ========================
// Tile 128(M) x 256(N), 8 warps (2M x 4N), warp tile 64x64.
// 3-stage cp.async ring; wait_group 1 normally, wait_group 0 on the FINAL
// iteration (tail-race fix: with only the last group pending, wait_group 1
// is a no-op and the stage could be read before its copy lands).

// ---------------- GEMM1: h = gelu(gather(xh) @ W1h + b1) -------------------
__global__ __launch_bounds__(256, 1) void gemm1_tc(const float* __restrict__ b1) {
    int e = blockIdx.z;
    int off = g_offsets[e];
    int cnt = g_offsets[e + 1] - off;
    int m0 = blockIdx.y * BM;
    if (m0 >= cnt) return;
    int n0 = blockIdx.x * BN;

    extern __shared__ __align__(16) char dsm[];
    uint32_t sb = smem_u32(dsm);
    __shared__ int stok[BM];

    int tid = threadIdx.x, wid = tid >> 5, lane = tid & 31;
    int tig = lane & 3, grp = lane >> 2;
    int mbase = (wid & 1) * 64;
    int nbase = (wid >> 1) * 64;

    if (tid < BM) {
        int m = m0 + tid;
        stok[tid] = (m < cnt) ? g_tok[off + m] : -1;
    }
    __syncthreads();

    int am = tid & 127;
    int t  = tid >> 7;
    int atok = stok[am];
    const uint32_t* asrc = g_xh + (size_t)((atok >= 0) ? atok : 0) * (kD / 2) + t * 8;
    uint32_t asz = (atok >= 0) ? 16u : 0u;
    uint32_t adst = sb + am * 80 + t * 32;
    int br = tid >> 4;
    int bj = tid & 15;
    const uint32_t* bsrc = g_w1h + ((size_t)e * (kD / 2) + br) * kF + n0 + bj * 4;
    uint32_t bdst = sb + A_STAGE_BYTES + br * (B_ROW_U32 * 4) + bj * 16;

    auto issue = [&](int st, int c) {
        uint32_t so = st * STAGE_BYTES;
        const uint32_t* as_ = asrc + c * 16;
        CP_ASYNC16Z(adst + so,      as_,     asz);
        CP_ASYNC16Z(adst + so + 16, as_ + 4, asz);
        const uint32_t* bs_ = bsrc + (size_t)c * 16 * kF;
#pragma unroll
        for (int q = 0; q < 4; q++)
            CP_ASYNC16(bdst + so + q * 256, bs_ + q * 64);
        CP_COMMIT();
    };

    int rowsel = lane & 15;
    int kh = lane >> 4;
    uint32_t a_lm0 = sb + (mbase + rowsel) * 80 + kh * 16;

    float acc[4][8][4];
#pragma unroll
    for (int i = 0; i < 4; i++)
#pragma unroll
        for (int j = 0; j < 8; j++)
#pragma unroll
            for (int q = 0; q < 4; q++) acc[i][j][q] = 0.f;

    constexpr int C2 = kD / BK2;   // 32
    issue(0, 0); issue(1, 1);

    for (int c = 0; c < C2; c++) {
        int st = c % STG;
        if (c + 1 == C2) { CP_WAIT0(); } else { CP_WAIT1(); }
        __syncthreads();
        if (c + 2 < C2) issue((c + 2) % STG, c + 2);

        uint32_t so = st * STAGE_BYTES;
        const uint32_t* Bst = (const uint32_t*)(dsm + so + A_STAGE_BYTES);
#pragma unroll
        for (int p = 0; p < 2; p++) {
            uint32_t af[4][4], bf[8][2];
            uint32_t ab = a_lm0 + so + p * 32;
#pragma unroll
            for (int mt = 0; mt < 4; mt++)
                ldmatrix_x4(af[mt], ab + mt * 16 * 80);
#pragma unroll
            for (int nt = 0; nt < 8; nt++) {
                int nc = nbase + nt * 8 + grp;
                bf[nt][0] = Bst[(p * 8 + tig) * B_ROW_U32 + nc];
                bf[nt][1] = Bst[(p * 8 + tig + 4) * B_ROW_U32 + nc];
            }
#pragma unroll
            for (int mt = 0; mt < 4; mt++)
#pragma unroll
                for (int nt = 0; nt < 8; nt++)
                    mma_f16(acc[mt][nt], af[mt][0], af[mt][1], af[mt][2], af[mt][3],
                            bf[nt][0], bf[nt][1]);
        }
    }

    // epilogue: bias + gelu, write fp16
    const float* bb = b1 + (size_t)e * kF + n0;
#pragma unroll
    for (int mt = 0; mt < 4; mt++) {
        int rbase = mbase + mt * 16 + grp;
#pragma unroll
        for (int h = 0; h < 2; h++) {
            int r = rbase + h * 8;
            int m = m0 + r;
            if (m < cnt) {
                __half* hrow = g_h + (size_t)(off + m) * kF + n0;
#pragma unroll
                for (int nt = 0; nt < 8; nt++) {
                    int cc = nbase + nt * 8 + tig * 2;
                    float vx = gelu_f(acc[mt][nt][h * 2 + 0] + bb[cc]);
                    float vy = gelu_f(acc[mt][nt][h * 2 + 1] + bb[cc + 1]);
                    *(uint32_t*)(hrow + cc) = h2(vx, vy);
                }
            }
        }
    }
}

// ---------------- GEMM2: out += w * (h @ W2h + b2) -------------------------
__global__ __launch_bounds__(256, 1) void gemm2_tc(const float* __restrict__ b2,
                                                   float* __restrict__ out) {
    int e = blockIdx.z;
    int off = g_offsets[e];
    int cnt = g_offsets[e + 1] - off;
    int m0 = blockIdx.y * BM;
    if (m0 >= cnt) return;
    int n0 = blockIdx.x * BN;

    extern __shared__ __align__(16) char dsm[];
    uint32_t sb = smem_u32(dsm);
    __shared__ int   stok[BM];
    __shared__ float swt[BM];

    int tid = threadIdx.x, wid = tid >> 5, lane = tid & 31;
    int tig = lane & 3, grp = lane >> 2;
    int mbase = (wid & 1) * 64;
    int nbase = (wid >> 1) * 64;

    if (tid < BM) {
        int m = m0 + tid;
        stok[tid] = (m < cnt) ? g_tok[off + m] : -1;
        swt[tid]  = (m < cnt) ? g_wt[off + m] : 0.f;
    }
    __syncthreads();

    int am = tid & 127;
    int t  = tid >> 7;
    bool avalid = (m0 + am) < cnt;
    const __half* asrc = g_h + (avalid ? (size_t)(off + m0 + am) * kF : 0) + t * 16;
    uint32_t asz = avalid ? 16u : 0u;
    uint32_t adst = sb + am * 80 + t * 32;
    int br = tid >> 4;
    int bj = tid & 15;
    const uint32_t* bsrc = g_w2h + ((size_t)e * (kF / 2) + br) * kD + n0 + bj * 4;
    uint32_t bdst = sb + A_STAGE_BYTES + br * (B_ROW_U32 * 4) + bj * 16;

    auto issue = [&](int st, int c) {
        uint32_t so = st * STAGE_BYTES;
        const __half* as_ = asrc + c * 32;
        CP_ASYNC16Z(adst + so,      as_,     asz);
        CP_ASYNC16Z(adst + so + 16, as_ + 8, asz);
        const uint32_t* bs_ = bsrc + (size_t)c * 16 * kD;
#pragma unroll
        for (int q = 0; q < 4; q++)
            CP_ASYNC16(bdst + so + q * 256, bs_ + q * 64);
        CP_COMMIT();
    };

    int rowsel = lane & 15;
    int kh = lane >> 4;
    uint32_t a_lm0 = sb + (mbase + rowsel) * 80 + kh * 16;

    float acc[4][8][4];
#pragma unroll
    for (int i = 0; i < 4; i++)
#pragma unroll
        for (int j = 0; j < 8; j++)
#pragma unroll
            for (int q = 0; q < 4; q++) acc[i][j][q] = 0.f;

    constexpr int C2 = kF / BK2;   // 128
    issue(0, 0); issue(1, 1);

    for (int c = 0; c < C2; c++) {
        int st = c % STG;
        if (c + 1 == C2) { CP_WAIT0(); } else { CP_WAIT1(); }
        __syncthreads();
        if (c + 2 < C2) issue((c + 2) % STG, c + 2);

        uint32_t so = st * STAGE_BYTES;
        const uint32_t* Bst = (const uint32_t*)(dsm + so + A_STAGE_BYTES);
#pragma unroll
        for (int p = 0; p < 2; p++) {
            uint32_t af[4][4], bf[8][2];
            uint32_t ab = a_lm0 + so + p * 32;
#pragma unroll
            for (int mt = 0; mt < 4; mt++)
                ldmatrix_x4(af[mt], ab + mt * 16 * 80);
#pragma unroll
            for (int nt = 0; nt < 8; nt++) {
                int nc = nbase + nt * 8 + grp;
                bf[nt][0] = Bst[(p * 8 + tig) * B_ROW_U32 + nc];
                bf[nt][1] = Bst[(p * 8 + tig + 4) * B_ROW_U32 + nc];
            }
#pragma unroll
            for (int mt = 0; mt < 4; mt++)
#pragma unroll
                for (int nt = 0; nt < 8; nt++)
                    mma_f16(acc[mt][nt], af[mt][0], af[mt][1], af[mt][2], af[mt][3],
                            bf[nt][0], bf[nt][1]);
        }
    }

    // epilogue: weighted atomic scatter (fp32)
    const float* bbv = b2 + (size_t)e * kD + n0;
#pragma unroll
    for (int mt = 0; mt < 4; mt++) {
        int rbase = mbase + mt * 16 + grp;
#pragma unroll
        for (int h = 0; h < 2; h++) {
            int r = rbase + h * 8;
            int m = m0 + r;
            if (m < cnt) {
                int   tok = stok[r];
                float w   = swt[r];
                float* orow = out + (size_t)tok * kD + n0;
#pragma unroll
                for (int nt = 0; nt < 8; nt++) {
                    int cc = nbase + nt * 8 + tig * 2;
                    atomicAdd(&orow[cc],     w * (acc[mt][nt][h * 2 + 0] + bbv[cc]));
                    atomicAdd(&orow[cc + 1], w * (acc[mt][nt][h * 2 + 1] + bbv[cc + 1]));
                }
            }
        }
    }
}

// ---------------- launch ----------------
extern "C" void kernel_launch(void* const* d_in, const int* in_sizes, int n_in,
                              void* d_out, int out_size) {
    const float* x  = (const float*)d_in[0];
    const float* Wg = (const float*)d_in[1];
    const float* bg = (const float*)d_in[2];
    const float* W1 = (const float*)d_in[3];
    const float* b1 = (const float*)d_in[4];
    const float* W2 = (const float*)d_in[5];
    const float* b2 = (const float*)d_in[6];
    float* out = (float*)d_out;

    cudaFuncSetAttribute(gemm1_tc, cudaFuncAttributeMaxDynamicSharedMemorySize, SMEM_BYTES);
    cudaFuncSetAttribute(gemm2_tc, cudaFuncAttributeMaxDynamicSharedMemorySize, SMEM_BYTES);

    cudaMemsetAsync(out, 0, (size_t)out_size * sizeof(float));
    init_kernel<<<1, 32>>>();
    gate_kernel<<<kTOK / 8, 256>>>(x, Wg, bg);
    convert_x<<<kTOK * (kD / 8) / 256, 256>>>(x);
    convert_w1<<<kE * (kD / 2) * (kF / 4) / 256, 256>>>(W1);
    convert_w2<<<kE * (kF / 2) * (kD / 4) / 256, 256>>>(W2);
    scan_kernel<<<1, 1>>>();
    scatter_kernel<<<kASSIGN / 256, 256>>>();
    gemm1_tc<<<dim3(kF / BN, kTOK / BM, kE), 256, SMEM_BYTES>>>(b1);
    gemm2_tc<<<dim3(kD / BN, kTOK / BM, kE), 256, SMEM_BYTES>>>(b2, out);
}

// round 10
// speedup vs baseline: 4.7678x; 1.0153x over previous
#include <cuda_runtime.h>
#include <cuda_fp16.h>
#include <cstdint>
#include <math.h>

// ---------------- problem constants ----------------
constexpr int kTOK = 8192;
constexpr int kD   = 1024;
constexpr int kF   = 4096;
constexpr int kE   = 8;
constexpr int kASSIGN = kTOK * 2;

constexpr int BM = 128, BN = 256;
constexpr int BK2 = 32;                    // K per pipeline stage (2 MMA phases)
constexpr int STG = 4;
constexpr int A_STAGE_BYTES = BM * 80;             // 10240
constexpr int B_ROW_U32     = 264;
constexpr int B_STAGE_BYTES = 16 * B_ROW_U32 * 4;  // 16896
constexpr int STAGE_BYTES   = A_STAGE_BYTES + B_STAGE_BYTES;   // 27136
constexpr int SMEM_BYTES    = STG * STAGE_BYTES;               // 108544

// ---------------- device scratch ----------------
__device__ int   g_topk_e[kASSIGN];
__device__ float g_topk_w[kASSIGN];
__device__ int   g_counts[kE];
__device__ int   g_offsets[kE + 1];
__device__ int   g_cursors[kE];
__device__ int   g_tok[kASSIGN];
__device__ float g_wt[kASSIGN];
__device__ __half   g_h[(size_t)kASSIGN * kF];
__device__ uint32_t g_w1h[(size_t)kE * (kD / 2) * kF];
__device__ uint32_t g_w2h[(size_t)kE * (kF / 2) * kD];
__device__ uint32_t g_xh[(size_t)kTOK * (kD / 2)];

// ---------------- helpers ----------------
__device__ __forceinline__ void mma_f16(float* c, uint32_t a0, uint32_t a1,
                                        uint32_t a2, uint32_t a3,
                                        uint32_t b0, uint32_t b1) {
    asm volatile("mma.sync.aligned.m16n8k16.row.col.f32.f16.f16.f32 "
                 "{%0,%1,%2,%3}, {%4,%5,%6,%7}, {%8,%9}, {%0,%1,%2,%3};"
                 : "+f"(c[0]), "+f"(c[1]), "+f"(c[2]), "+f"(c[3])
                 : "r"(a0), "r"(a1), "r"(a2), "r"(a3), "r"(b0), "r"(b1));
}
__device__ __forceinline__ void ldmatrix_x4(uint32_t* r, uint32_t addr) {
    asm volatile("ldmatrix.sync.aligned.m8n8.x4.shared.b16 {%0,%1,%2,%3}, [%4];"
                 : "=r"(r[0]), "=r"(r[1]), "=r"(r[2]), "=r"(r[3]) : "r"(addr));
}
__device__ __forceinline__ uint32_t h2(float a, float b) {
    __half2 h = __floats2half2_rn(a, b);
    return *(uint32_t*)&h;
}
__device__ __forceinline__ float gelu_f(float v) {
    return 0.5f * v * (1.0f + erff(v * 0.70710678118654752f));
}
__device__ __forceinline__ uint32_t smem_u32(const void* p) {
    uint32_t a;
    asm("{ .reg .u64 t; cvta.to.shared.u64 t, %1; cvt.u32.u64 %0, t; }"
        : "=r"(a) : "l"(p));
    return a;
}
#define CP_ASYNC16(dst, src) \
    asm volatile("cp.async.cg.shared.global [%0], [%1], 16;" :: "r"(dst), "l"(src))
#define CP_ASYNC16Z(dst, src, sz) \
    asm volatile("cp.async.cg.shared.global [%0], [%1], 16, %2;" :: "r"(dst), "l"(src), "r"(sz))
#define CP_COMMIT() asm volatile("cp.async.commit_group;" ::: "memory")
#define CP_WAIT2()  asm volatile("cp.async.wait_group 2;" ::: "memory")
#define CP_WAIT1()  asm volatile("cp.async.wait_group 1;" ::: "memory")
#define CP_WAIT0()  asm volatile("cp.async.wait_group 0;" ::: "memory")

// Tail-exact wait: guarantee the group for chunk c has completed.
// Pending groups at wait time are {c .. min(c+2, C2-1)}.
#define PIPE_WAIT(c, C2) do {                 \
    if ((c) + 1 == (C2))      { CP_WAIT0(); } \
    else if ((c) + 2 == (C2)) { CP_WAIT1(); } \
    else                      { CP_WAIT2(); } \
} while (0)

// ---------------- routing kernels ----------------
__global__ void init_kernel() {
    int i = threadIdx.x;
    if (i < kE) { g_counts[i] = 0; g_cursors[i] = 0; }
}

// gate + fused x->fp16 conversion (x is read here anyway)
__global__ void gate_kernel(const float* __restrict__ x, const float* __restrict__ Wg,
                            const float* __restrict__ bg) {
    int w = (blockIdx.x * blockDim.x + threadIdx.x) >> 5;
    int lane = threadIdx.x & 31;
    if (w >= kTOK) return;
    const float* xr = x + (size_t)w * kD;
    uint32_t* xh = g_xh + (size_t)w * (kD / 2);
    float acc[kE];
#pragma unroll
    for (int e = 0; e < kE; e++) acc[e] = 0.f;
    for (int d = lane * 4; d < kD; d += 128) {
        float4 xv = *(const float4*)(xr + d);
        // fused fp16 emit (coalesced 8B per lane)
        uint2 hv = make_uint2(h2(xv.x, xv.y), h2(xv.z, xv.w));
        *(uint2*)(xh + d / 2) = hv;
#pragma unroll
        for (int e = 0; e < kE; e++) {
            float4 wv = *(const float4*)(Wg + e * kD + d);
            acc[e] += xv.x * wv.x + xv.y * wv.y + xv.z * wv.z + xv.w * wv.w;
        }
    }
#pragma unroll
    for (int e = 0; e < kE; e++)
#pragma unroll
        for (int o = 16; o; o >>= 1) acc[e] += __shfl_xor_sync(0xffffffffu, acc[e], o);
    if (lane == 0) {
        float l[kE];
#pragma unroll
        for (int e = 0; e < kE; e++) l[e] = acc[e] + bg[e];
        int i1 = 0;
#pragma unroll
        for (int e = 1; e < kE; e++) if (l[e] > l[i1]) i1 = e;
        int i2 = (i1 == 0) ? 1 : 0;
#pragma unroll
        for (int e = 0; e < kE; e++) if (e != i1 && l[e] > l[i2]) i2 = e;
        float w1 = 1.f / (1.f + expf(l[i2] - l[i1]));
        g_topk_e[2 * w] = i1; g_topk_e[2 * w + 1] = i2;
        g_topk_w[2 * w] = w1; g_topk_w[2 * w + 1] = 1.f - w1;
        atomicAdd(&g_counts[i1], 1);
        atomicAdd(&g_counts[i2], 1);
    }
}

__global__ void scan_kernel() {
    int s = 0;
#pragma unroll
    for (int e = 0; e < kE; e++) { g_offsets[e] = s; s += g_counts[e]; }
    g_offsets[kE] = s;
}

__global__ void scatter_kernel() {
    int i = blockIdx.x * blockDim.x + threadIdx.x;
    if (i >= kASSIGN) return;
    int e = g_topk_e[i];
    int pos = g_offsets[e] + atomicAdd(&g_cursors[e], 1);
    g_tok[pos] = i >> 1;
    g_wt[pos] = g_topk_w[i];
}

// ---------------- merged weight conversion (W1 + W2, one launch) -----------
constexpr int W1_BLOCKS = kE * (kD / 2) * (kF / 4) / 256;   // 16384
constexpr int W2_BLOCKS = kE * (kF / 2) * (kD / 4) / 256;   // 16384
__global__ void convert_w(const float* __restrict__ W1, const float* __restrict__ W2) {
    if (blockIdx.x < W1_BLOCKS) {
        int idx = blockIdx.x * blockDim.x + threadIdx.x;
        int n4 = idx & 1023;
        int r  = idx >> 10;
        int k2 = r & 511;
        int e  = r >> 9;
        const float* base = W1 + ((size_t)e * kD + 2 * k2) * kF + n4 * 4;
        float4 a = *(const float4*)base;
        float4 b = *(const float4*)(base + kF);
        uint4 o = make_uint4(h2(a.x, b.x), h2(a.y, b.y), h2(a.z, b.z), h2(a.w, b.w));
        *(uint4*)(g_w1h + ((size_t)e * (kD / 2) + k2) * kF + n4 * 4) = o;
    } else {
        int idx = (blockIdx.x - W1_BLOCKS) * blockDim.x + threadIdx.x;
        int n4 = idx & 255;
        int r  = idx >> 8;
        int k2 = r & 2047;
        int e  = r >> 11;
        const float* base = W2 + ((size_t)e * kF + 2 * k2) * kD + n4 * 4;
        float4 a = *(const float4*)base;
        float4 b = *(const float4*)(base + kD);
        uint4 o = make_uint4(h2(a.x, b.x), h2(a.y, b.y), h2(a.z, b.z), h2(a.w, b.w));
        *(uint4*)(g_w2h + ((size_t)e * (kF / 2) + k2) * kD + n4 * 4) = o;
    }
}

// ======================= fp16 mma.sync GEMM kernels ========================
// Tile 128(M) x 256(N), 8 warps (2M x 4N), warp tile 64x64.
// 4-stage cp.async ring, 3 chunks in flight, exact tail waits.

// ---------------- GEMM1: h = gelu(gather(xh) @ W1h + b1) -------------------
__global__ __launch_bounds__(256, 1) void gemm1_tc(const float* __restrict__ b1) {
    int e = blockIdx.z;
    int off = g_offsets[e];
    int cnt = g_offsets[e + 1] - off;
    int m0 = blockIdx.y * BM;
    if (m0 >= cnt) return;
    int n0 = blockIdx.x * BN;

    extern __shared__ __align__(16) char dsm[];
    uint32_t sb = smem_u32(dsm);
    __shared__ int stok[BM];

    int tid = threadIdx.x, wid = tid >> 5, lane = tid & 31;
    int tig = lane & 3, grp = lane >> 2;
    int mbase = (wid & 1) * 64;
    int nbase = (wid >> 1) * 64;

    if (tid < BM) {
        int m = m0 + tid;
        stok[tid] = (m < cnt) ? g_tok[off + m] : -1;
    }
    __syncthreads();

    int am = tid & 127;
    int t  = tid >> 7;
    int atok = stok[am];
    const uint32_t* asrc = g_xh + (size_t)((atok >= 0) ? atok : 0) * (kD / 2) + t * 8;
    uint32_t asz = (atok >= 0) ? 16u : 0u;
    uint32_t adst = sb + am * 80 + t * 32;
    int br = tid >> 4;
    int bj = tid & 15;
    const uint32_t* bsrc = g_w1h + ((size_t)e * (kD / 2) + br) * kF + n0 + bj * 4;
    uint32_t bdst = sb + A_STAGE_BYTES + br * (B_ROW_U32 * 4) + bj * 16;

    auto issue = [&](int st, int c) {
        uint32_t so = st * STAGE_BYTES;
        const uint32_t* as_ = asrc + c * 16;
        CP_ASYNC16Z(adst + so,      as_,     asz);
        CP_ASYNC16Z(adst + so + 16, as_ + 4, asz);
        const uint32_t* bs_ = bsrc + (size_t)c * 16 * kF;
#pragma unroll
        for (int q = 0; q < 4; q++)
            CP_ASYNC16(bdst + so + q * 256, bs_ + q * 64);
        CP_COMMIT();
    };

    int rowsel = lane & 15;
    int kh = lane >> 4;
    uint32_t a_lm0 = sb + (mbase + rowsel) * 80 + kh * 16;

    float acc[4][8][4];
#pragma unroll
    for (int i = 0; i < 4; i++)
#pragma unroll
        for (int j = 0; j < 8; j++)
#pragma unroll
            for (int q = 0; q < 4; q++) acc[i][j][q] = 0.f;

    constexpr int C2 = kD / BK2;   // 32
    issue(0, 0); issue(1, 1); issue(2, 2);

    for (int c = 0; c < C2; c++) {
        int st = c % STG;
        PIPE_WAIT(c, C2);
        __syncthreads();
        if (c + 3 < C2) issue((c + 3) % STG, c + 3);

        uint32_t so = st * STAGE_BYTES;
        const uint32_t* Bst = (const uint32_t*)(dsm + so + A_STAGE_BYTES);
#pragma unroll
        for (int p = 0; p < 2; p++) {
            uint32_t af[4][4], bf[8][2];
            uint32_t ab = a_lm0 + so + p * 32;
#pragma unroll
            for (int mt = 0; mt < 4; mt++)
                ldmatrix_x4(af[mt], ab + mt * 16 * 80);
#pragma unroll
            for (int nt = 0; nt < 8; nt++) {
                int nc = nbase + nt * 8 + grp;
                bf[nt][0] = Bst[(p * 8 + tig) * B_ROW_U32 + nc];
                bf[nt][1] = Bst[(p * 8 + tig + 4) * B_ROW_U32 + nc];
            }
#pragma unroll
            for (int mt = 0; mt < 4; mt++)
#pragma unroll
                for (int nt = 0; nt < 8; nt++)
                    mma_f16(acc[mt][nt], af[mt][0], af[mt][1], af[mt][2], af[mt][3],
                            bf[nt][0], bf[nt][1]);
        }
    }

    // epilogue: bias + gelu, write fp16
    const float* bb = b1 + (size_t)e * kF + n0;
#pragma unroll
    for (int mt = 0; mt < 4; mt++) {
        int rbase = mbase + mt * 16 + grp;
#pragma unroll
        for (int h = 0; h < 2; h++) {
            int r = rbase + h * 8;
            int m = m0 + r;
            if (m < cnt) {
                __half* hrow = g_h + (size_t)(off + m) * kF + n0;
#pragma unroll
                for (int nt = 0; nt < 8; nt++) {
                    int cc = nbase + nt * 8 + tig * 2;
                    float vx = gelu_f(acc[mt][nt][h * 2 + 0] + bb[cc]);
                    float vy = gelu_f(acc[mt][nt][h * 2 + 1] + bb[cc + 1]);
                    *(uint32_t*)(hrow + cc) = h2(vx, vy);
                }
            }
        }
    }
}

// ---------------- GEMM2: out += w * (h @ W2h + b2) -------------------------
__global__ __launch_bounds__(256, 1) void gemm2_tc(const float* __restrict__ b2,
                                                   float* __restrict__ out) {
    int e = blockIdx.z;
    int off = g_offsets[e];
    int cnt = g_offsets[e + 1] - off;
    int m0 = blockIdx.y * BM;
    if (m0 >= cnt) return;
    int n0 = blockIdx.x * BN;

    extern __shared__ __align__(16) char dsm[];
    uint32_t sb = smem_u32(dsm);
    __shared__ int   stok[BM];
    __shared__ float swt[BM];

    int tid = threadIdx.x, wid = tid >> 5, lane = tid & 31;
    int tig = lane & 3, grp = lane >> 2;
    int mbase = (wid & 1) * 64;
    int nbase = (wid >> 1) * 64;

    if (tid < BM) {
        int m = m0 + tid;
        stok[tid] = (m < cnt) ? g_tok[off + m] : -1;
        swt[tid]  = (m < cnt) ? g_wt[off + m] : 0.f;
    }
    __syncthreads();

    int am = tid & 127;
    int t  = tid >> 7;
    bool avalid = (m0 + am) < cnt;
    const __half* asrc = g_h + (avalid ? (size_t)(off + m0 + am) * kF : 0) + t * 16;
    uint32_t asz = avalid ? 16u : 0u;
    uint32_t adst = sb + am * 80 + t * 32;
    int br = tid >> 4;
    int bj = tid & 15;
    const uint32_t* bsrc = g_w2h + ((size_t)e * (kF / 2) + br) * kD + n0 + bj * 4;
    uint32_t bdst = sb + A_STAGE_BYTES + br * (B_ROW_U32 * 4) + bj * 16;

    auto issue = [&](int st, int c) {
        uint32_t so = st * STAGE_BYTES;
        const __half* as_ = asrc + c * 32;
        CP_ASYNC16Z(adst + so,      as_,     asz);
        CP_ASYNC16Z(adst + so + 16, as_ + 8, asz);
        const uint32_t* bs_ = bsrc + (size_t)c * 16 * kD;
#pragma unroll
        for (int q = 0; q < 4; q++)
            CP_ASYNC16(bdst + so + q * 256, bs_ + q * 64);
        CP_COMMIT();
    };

    int rowsel = lane & 15;
    int kh = lane >> 4;
    uint32_t a_lm0 = sb + (mbase + rowsel) * 80 + kh * 16;

    float acc[4][8][4];
#pragma unroll
    for (int i = 0; i < 4; i++)
#pragma unroll
        for (int j = 0; j < 8; j++)
#pragma unroll
            for (int q = 0; q < 4; q++) acc[i][j][q] = 0.f;

    constexpr int C2 = kF / BK2;   // 128
    issue(0, 0); issue(1, 1); issue(2, 2);

    for (int c = 0; c < C2; c++) {
        int st = c % STG;
        PIPE_WAIT(c, C2);
        __syncthreads();
        if (c + 3 < C2) issue((c + 3) % STG, c + 3);

        uint32_t so = st * STAGE_BYTES;
        const uint32_t* Bst = (const uint32_t*)(dsm + so + A_STAGE_BYTES);
#pragma unroll
        for (int p = 0; p < 2; p++) {
            uint32_t af[4][4], bf[8][2];
            uint32_t ab = a_lm0 + so + p * 32;
#pragma unroll
            for (int mt = 0; mt < 4; mt++)
                ldmatrix_x4(af[mt], ab + mt * 16 * 80);
#pragma unroll
            for (int nt = 0; nt < 8; nt++) {
                int nc = nbase + nt * 8 + grp;
                bf[nt][0] = Bst[(p * 8 + tig) * B_ROW_U32 + nc];
                bf[nt][1] = Bst[(p * 8 + tig + 4) * B_ROW_U32 + nc];
            }
#pragma unroll
            for (int mt = 0; mt < 4; mt++)
#pragma unroll
                for (int nt = 0; nt < 8; nt++)
                    mma_f16(acc[mt][nt], af[mt][0], af[mt][1], af[mt][2], af[mt][3],
                            bf[nt][0], bf[nt][1]);
        }
    }

    // epilogue: weighted atomic scatter (fp32)
    const float* bbv = b2 + (size_t)e * kD + n0;
#pragma unroll
    for (int mt = 0; mt < 4; mt++) {
        int rbase = mbase + mt * 16 + grp;
#pragma unroll
        for (int h = 0; h < 2; h++) {
            int r = rbase + h * 8;
            int m = m0 + r;
            if (m < cnt) {
                int   tok = stok[r];
                float w   = swt[r];
                float* orow = out + (size_t)tok * kD + n0;
#pragma unroll
                for (int nt = 0; nt < 8; nt++) {
                    int cc = nbase + nt * 8 + tig * 2;
                    atomicAdd(&orow[cc],     w * (acc[mt][nt][h * 2 + 0] + bbv[cc]));
                    atomicAdd(&orow[cc + 1], w * (acc[mt][nt][h * 2 + 1] + bbv[cc + 1]));
                }
            }
        }
    }
}

// ---------------- launch ----------------
extern "C" void kernel_launch(void* const* d_in, const int* in_sizes, int n_in,
                              void* d_out, int out_size) {
    const float* x  = (const float*)d_in[0];
    const float* Wg = (const float*)d_in[1];
    const float* bg = (const float*)d_in[2];
    const float* W1 = (const float*)d_in[3];
    const float* b1 = (const float*)d_in[4];
    const float* W2 = (const float*)d_in[5];
    const float* b2 = (const float*)d_in[6];
    float* out = (float*)d_out;

    cudaFuncSetAttribute(gemm1_tc, cudaFuncAttributeMaxDynamicSharedMemorySize, SMEM_BYTES);
    cudaFuncSetAttribute(gemm2_tc, cudaFuncAttributeMaxDynamicSharedMemorySize, SMEM_BYTES);

    cudaMemsetAsync(out, 0, (size_t)out_size * sizeof(float));
    init_kernel<<<1, 32>>>();
    gate_kernel<<<kTOK / 8, 256>>>(x, Wg, bg);          // also emits g_xh
    convert_w<<<W1_BLOCKS + W2_BLOCKS, 256>>>(W1, W2);
    scan_kernel<<<1, 1>>>();
    scatter_kernel<<<kASSIGN / 256, 256>>>();
    gemm1_tc<<<dim3(kF / BN, kTOK / BM, kE), 256, SMEM_BYTES>>>(b1);
    gemm2_tc<<<dim3(kD / BN, kTOK / BM, kE), 256, SMEM_BYTES>>>(b2, out);
}